// round 13
// baseline (speedup 1.0000x reference)
#include <cuda_runtime.h>
#include <cstdint>

#define NN 50000
#define NE 800000
#define NG 512

// ---------------- device scratch (static, no runtime alloc) ----------------
__device__ float g_h0[NN * 128];
__device__ float g_h1[NN * 128];
__device__ float g_P [NN * 512];
__device__ float g_Wcat[512 * 128];
__device__ float g_bcat[512];
__device__ float g_pool[NG * 128];
__device__ float g_t0g[NG * 256];
__device__ float g_t1g[NG * 256];
__device__ float g_gfin[NG * 128];

// ---------------- helpers ----------------
typedef unsigned long long u64;
__device__ __forceinline__ u64 pk2(float lo, float hi) {
    u64 r; asm("mov.b64 %0,{%1,%2};" : "=l"(r) : "f"(lo), "f"(hi)); return r;
}
__device__ __forceinline__ float2 up2(u64 v) {
    float2 r; asm("mov.b64 {%0,%1},%2;" : "=f"(r.x), "=f"(r.y) : "l"(v)); return r;
}
__device__ __forceinline__ u64 ffma2(u64 a, u64 b, u64 c) {
    u64 d; asm("fma.rn.f32x2 %0,%1,%2,%3;" : "=l"(d) : "l"(a), "l"(b), "l"(c)); return d;
}
union F4U { float4 f4; u64 u[2]; float f[4]; };

__device__ __forceinline__ void red4(float* addr, float4 v) {
    asm volatile("red.global.add.v4.f32 [%0], {%1,%2,%3,%4};"
                 :: "l"(addr), "f"(v.x), "f"(v.y), "f"(v.z), "f"(v.w) : "memory");
}
__device__ __forceinline__ void red2(float* addr, float2 v) {
    asm volatile("red.global.add.v2.f32 [%0], {%1,%2};"
                 :: "l"(addr), "f"(v.x), "f"(v.y) : "memory");
}
__device__ __forceinline__ void cpasync16(unsigned saddr, const void* gaddr) {
    asm volatile("cp.async.cg.shared.global [%0], [%1], 16;" :: "r"(saddr), "l"(gaddr));
}
__device__ __forceinline__ void cpcommit() { asm volatile("cp.async.commit_group;"); }
__device__ __forceinline__ void cpwait0()  { asm volatile("cp.async.wait_group 0;"); }

__device__ __forceinline__ float sigm(float x) { return 1.f / (1.f + __expf(-x)); }
__device__ __forceinline__ float softp(float x) {
    return fmaxf(x, 0.f) + __logf(1.f + __expf(-fabsf(x)));
}
__device__ __forceinline__ unsigned f2tf(float x) {
    unsigned r; asm("cvt.rna.tf32.f32 %0, %1;" : "=r"(r) : "f"(x)); return r;
}
__device__ __forceinline__ void mma_tf32_16n8k8(float* c, unsigned a0, unsigned a1,
                                                unsigned a2, unsigned a3,
                                                unsigned b0, unsigned b1) {
    asm volatile(
        "mma.sync.aligned.m16n8k8.row.col.f32.tf32.tf32.f32 "
        "{%0,%1,%2,%3}, {%4,%5,%6,%7}, {%8,%9}, {%0,%1,%2,%3};"
        : "+f"(c[0]), "+f"(c[1]), "+f"(c[2]), "+f"(c[3])
        : "r"(a0), "r"(a1), "r"(a2), "r"(a3), "r"(b0), "r"(b1));
}

// ---------------- pack concatenated projection weights ----------------
__global__ void pack_wcat(const float* __restrict__ Wf, const float* __restrict__ Ws,
                          const float* __restrict__ bf, const float* __restrict__ bs,
                          float* __restrict__ Wcat, float* __restrict__ bcat, int layer) {
    int idx = blockIdx.x * blockDim.x + threadIdx.x;
    if (idx < 512) {
        float b = 0.f;
        if (idx < 128) b = bf[layer * 128 + idx];
        else if (idx < 256) b = bs[layer * 128 + idx - 128];
        bcat[idx] = b;
    }
    if (idx >= 512 * 128) return;
    int n = idx >> 7, k = idx & 127;
    const float* W; int o, koff;
    if      (n < 128) { W = Wf; o = n;       koff = 0;   }
    else if (n < 256) { W = Ws; o = n - 128; koff = 0;   }
    else if (n < 384) { W = Wf; o = n - 256; koff = 128; }
    else              { W = Ws; o = n - 384; koff = 128; }
    Wcat[idx] = W[((size_t)(layer * 128 + o)) * 320 + koff + k];
}

// ---------------- HMMA tf32 GEMM (R10 win, unchanged) ----------------
#define GLDS 36
#define HMMA_SMEM (2 * 2 * 128 * GLDS * 4)   // 73728 bytes

__global__ void __launch_bounds__(256) hmma_gemm(
    const float* __restrict__ A, const float* __restrict__ B,
    const float* __restrict__ bias, const float* __restrict__ res,
    float* __restrict__ C, int M, int N, int K, int relu) {
    extern __shared__ float sm[];
    float* sA = sm;
    float* sB = sm + 2 * 128 * GLDS;
    unsigned saA = (unsigned)__cvta_generic_to_shared(sA);
    unsigned saB = (unsigned)__cvta_generic_to_shared(sB);

    int tid = threadIdx.x, wid = tid >> 5, lane = tid & 31;
    int warp_m = wid >> 2, warp_n = wid & 3;
    int r0 = lane >> 2, q = lane & 3;
    int m0 = blockIdx.y * 128, n0 = blockIdx.x * 128;

    auto stage = [&](int k0, int bb) {
#pragma unroll
        for (int t = 0; t < 4; t++) {
            int idx = tid + t * 256;
            int row = idx >> 3, c4 = idx & 7;
            int ar = m0 + row;
            if (ar < M)
                cpasync16(saA + (unsigned)(((bb * 128 + row) * GLDS + c4 * 4) * 4),
                          A + (size_t)ar * K + k0 + c4 * 4);
            cpasync16(saB + (unsigned)(((bb * 128 + row) * GLDS + c4 * 4) * 4),
                      B + (size_t)(n0 + row) * K + k0 + c4 * 4);
        }
    };

    float acc[4][4][4];
#pragma unroll
    for (int mt = 0; mt < 4; mt++)
#pragma unroll
        for (int nt = 0; nt < 4; nt++)
#pragma unroll
            for (int j = 0; j < 4; j++) acc[mt][nt][j] = 0.f;

    int nst = K >> 5;
    stage(0, 0); cpcommit();
    for (int s = 0; s < nst; s++) {
        cpwait0();
        __syncthreads();
        if (s + 1 < nst) { stage((s + 1) << 5, (s + 1) & 1); cpcommit(); }
        int bb = s & 1;
        const float* bA = sA + bb * 128 * GLDS;
        const float* bBp = sB + bb * 128 * GLDS;
#pragma unroll
        for (int ks = 0; ks < 4; ks++) {
            int k = ks * 8;
            unsigned af[4][4], bf4[4][2];
#pragma unroll
            for (int mt = 0; mt < 4; mt++) {
                const float* ap = bA + (warp_m * 64 + mt * 16 + r0) * GLDS + k + q;
                af[mt][0] = f2tf(ap[0]);
                af[mt][1] = f2tf(ap[8 * GLDS]);
                af[mt][2] = f2tf(ap[4]);
                af[mt][3] = f2tf(ap[8 * GLDS + 4]);
            }
#pragma unroll
            for (int nt = 0; nt < 4; nt++) {
                const float* bp = bBp + (warp_n * 32 + nt * 8 + r0) * GLDS + k + q;
                bf4[nt][0] = f2tf(bp[0]);
                bf4[nt][1] = f2tf(bp[4]);
            }
#pragma unroll
            for (int mt = 0; mt < 4; mt++)
#pragma unroll
                for (int nt = 0; nt < 4; nt++)
                    mma_tf32_16n8k8(acc[mt][nt], af[mt][0], af[mt][1], af[mt][2], af[mt][3],
                                    bf4[nt][0], bf4[nt][1]);
        }
        __syncthreads();
    }

#pragma unroll
    for (int mt = 0; mt < 4; mt++) {
#pragma unroll
        for (int half = 0; half < 2; half++) {
            int row = m0 + warp_m * 64 + mt * 16 + r0 + half * 8;
            if (row >= M) continue;
#pragma unroll
            for (int nt = 0; nt < 4; nt++) {
                int col = n0 + warp_n * 32 + nt * 8 + 2 * q;
                float v0 = acc[mt][nt][half * 2 + 0] + bias[col];
                float v1 = acc[mt][nt][half * 2 + 1] + bias[col + 1];
                if (res) {
                    float2 rv = *(const float2*)(res + (size_t)row * N + col);
                    v0 += rv.x; v1 += rv.y;
                }
                if (relu) { v0 = fmaxf(v0, 0.f); v1 = fmaxf(v1, 0.f); }
                *(float2*)(C + (size_t)row * N + col) = make_float2(v0, v1);
            }
        }
    }
}

// ---------------- SGEMM fp32 (graph-level, small) ----------------
__global__ void __launch_bounds__(256) sgemm_bt(
    const float* __restrict__ A, const float* __restrict__ B,
    const float* __restrict__ bias, const float* __restrict__ res,
    float* __restrict__ C, int M, int N, int K, int relu) {
    __shared__ float As[8][128];
    __shared__ float Bs[8][128];
    int tid = threadIdx.x;
    int m0 = blockIdx.y * 128;
    int n0 = blockIdx.x * 128;
    int tx = tid & 15, ty = tid >> 4;
    int lr = tid >> 1;
    int lk = (tid & 1) * 4;

    u64 acc[8][4];
#pragma unroll
    for (int i = 0; i < 8; i++)
#pragma unroll
        for (int j = 0; j < 4; j++) acc[i][j] = 0ull;

    for (int k0 = 0; k0 < K; k0 += 8) {
        float4 av = make_float4(0.f, 0.f, 0.f, 0.f);
        int arow = m0 + lr;
        if (arow < M) av = *(const float4*)(A + (size_t)arow * K + k0 + lk);
        As[lk + 0][lr] = av.x; As[lk + 1][lr] = av.y;
        As[lk + 2][lr] = av.z; As[lk + 3][lr] = av.w;
        float4 bv = *(const float4*)(B + (size_t)(n0 + lr) * K + k0 + lk);
        Bs[lk + 0][lr] = bv.x; Bs[lk + 1][lr] = bv.y;
        Bs[lk + 2][lr] = bv.z; Bs[lk + 3][lr] = bv.w;
        __syncthreads();
#pragma unroll
        for (int k = 0; k < 8; k++) {
            F4U b0, b1;
            b0.f4 = *(const float4*)&Bs[k][tx * 8];
            b1.f4 = *(const float4*)&Bs[k][tx * 8 + 4];
            float4 a0 = *(const float4*)&As[k][ty * 8];
            float4 a1 = *(const float4*)&As[k][ty * 8 + 4];
            float a[8] = {a0.x, a0.y, a0.z, a0.w, a1.x, a1.y, a1.z, a1.w};
#pragma unroll
            for (int i = 0; i < 8; i++) {
                u64 ai = pk2(a[i], a[i]);
                acc[i][0] = ffma2(ai, b0.u[0], acc[i][0]);
                acc[i][1] = ffma2(ai, b0.u[1], acc[i][1]);
                acc[i][2] = ffma2(ai, b1.u[0], acc[i][2]);
                acc[i][3] = ffma2(ai, b1.u[1], acc[i][3]);
            }
        }
        __syncthreads();
    }

#pragma unroll
    for (int i = 0; i < 8; i++) {
        int row = m0 + ty * 8 + i;
        if (row >= M) continue;
        int n = n0 + tx * 8;
        float o[8];
#pragma unroll
        for (int j2 = 0; j2 < 4; j2++) {
            float2 v = up2(acc[i][j2]);
            o[2 * j2] = v.x; o[2 * j2 + 1] = v.y;
        }
#pragma unroll
        for (int j = 0; j < 8; j++) {
            float v = o[j] + bias[n + j];
            if (res) v += res[(size_t)row * N + n + j];
            if (relu) v = fmaxf(v, 0.f);
            o[j] = v;
        }
        *(float4*)(C + (size_t)row * N + n)     = make_float4(o[0], o[1], o[2], o[3]);
        *(float4*)(C + (size_t)row * N + n + 4) = make_float4(o[4], o[5], o[6], o[7]);
    }
}

// ---------------- edge kernel v9: HMMA tf32 + cp.async-prefetched P gathers ----------------
// smem (floats): sP [2][16 edges][520]  (fd|sd|fs|ss, 512 data + 8 pad)  = 16640
//                sEa [2][16][68]                                          = 2176
//                sIdx [2][32] ints                                        = 64
#define EV9_EA   16640
#define EV9_IDX  18816
#define EV9_SMEM ((18816 + 64) * 4)   // 75520 bytes

__global__ void __launch_bounds__(256, 2) edge_hmma_kernel(
    const float* __restrict__ Pall, const int* __restrict__ ei,
    const float* __restrict__ ea, const float* __restrict__ Wf,
    const float* __restrict__ Ws, int layer, float* __restrict__ hout) {
    extern __shared__ float smf[];
    float* sP  = smf;
    float* sEa = smf + EV9_EA;
    int*   sIdx = (int*)(smf + EV9_IDX);
    unsigned sbase = (unsigned)__cvta_generic_to_shared(smf);

    int tid = threadIdx.x, w = tid >> 5, lane = tid & 31;
    int q = lane & 3, r0 = lane >> 2;

    // persistent B fragments (register-resident, R10 layout)
    unsigned bfr[4][8][2];
#pragma unroll
    for (int nt = 0; nt < 4; nt++) {
        int j = w * 16 + (nt & 1) * 8 + r0;
        const float* Wp = ((nt < 2) ? Wf : Ws) + (size_t)(layer * 128 + j) * 320 + 256;
#pragma unroll
        for (int ks = 0; ks < 8; ks++) {
            bfr[nt][ks][0] = f2tf(__ldg(Wp + ks * 8 + q));
            bfr[nt][ks][1] = f2tf(__ldg(Wp + ks * 8 + q + 4));
        }
    }

    const int NT = NE / 16;
    int nbs = gridDim.x;
    int tile = blockIdx.x;

    // stage tile t into buffer bb: EA row + idx + full P working set via cp.async
    auto stage = [&](int t, int bb) {
        int e0 = t << 4;
        int row = tid >> 4, c8 = tid & 15;     // this thread: edge `row`, 16B-chunk group c8
        int sN = __ldg(ei + e0 + row);
        int dN = __ldg(ei + NE + e0 + row);
        if (tid < 32) sIdx[bb * 32 + tid] = __ldg(ei + (tid < 16 ? 0 : NE) + e0 + (tid & 15));
        // EA chunk (one 16B per thread)
        cpasync16(sbase + (unsigned)((EV9_EA + (bb * 16 + row) * 68) * 4) + c8 * 16,
                  ea + (size_t)(e0 + row) * 64 + c8 * 4);
        // P chunks: 8 x 16B per thread -> 2KB per edge (fd|sd|fs|ss)
        unsigned prow = sbase + (unsigned)(((bb * 16 + row) * 520) * 4);
#pragma unroll
        for (int i = 0; i < 8; i++) {
            int cidx = c8 * 8 + i;          // 0..127
            int seg = cidx >> 5;            // 0=fd 1=sd 2=fs 3=ss
            int o = cidx & 31;              // 16B unit within segment
            int node = (seg < 2) ? dN : sN;
            cpasync16(prow + (unsigned)((seg * 128 + o * 4) * 4),
                      Pall + (size_t)node * 512 + seg * 128 + o * 4);
        }
    };

    if (tile < NT) stage(tile, 0);
    cpcommit();

    int buf = 0;
    for (; tile < NT; tile += nbs) {
        cpwait0();
        __syncthreads();                  // data(tile) visible; prev iter compute done
        int nxt = tile + nbs;
        if (nxt < NT) stage(nxt, buf ^ 1);
        cpcommit();

        // ---- tensor-core GEMM: 16 edges x 64 cols (this warp) ----
        float acc[4][4];
#pragma unroll
        for (int nt = 0; nt < 4; nt++)
#pragma unroll
            for (int j = 0; j < 4; j++) acc[nt][j] = 0.f;

        const float* eb = sEa + buf * 16 * 68;
#pragma unroll
        for (int ks = 0; ks < 8; ks++) {
            unsigned a0 = f2tf(eb[r0 * 68 + ks * 8 + q]);
            unsigned a1 = f2tf(eb[(r0 + 8) * 68 + ks * 8 + q]);
            unsigned a2 = f2tf(eb[r0 * 68 + ks * 8 + q + 4]);
            unsigned a3 = f2tf(eb[(r0 + 8) * 68 + ks * 8 + q + 4]);
#pragma unroll
            for (int nt = 0; nt < 4; nt++)
                mma_tf32_16n8k8(acc[nt], a0, a1, a2, a3, bfr[nt][ks][0], bfr[nt][ks][1]);
        }

        // ---- epilogue: P from smem (prefetched), activate, scatter ----
        const float* pb = sP + (size_t)buf * 16 * 520;
        const int* idxb = sIdx + buf * 32;
#pragma unroll
        for (int nt = 0; nt < 2; nt++) {
#pragma unroll
            for (int half = 0; half < 2; half++) {
                int row = r0 + half * 8;
                int dN = idxb[16 + row];
                const float* rp = pb + row * 520;
                int j = w * 16 + nt * 8 + 2 * q;
                float2 fd  = *(const float2*)(rp + j);
                float2 sd  = *(const float2*)(rp + 128 + j);
                float2 fs2 = *(const float2*)(rp + 256 + j);
                float2 ss2 = *(const float2*)(rp + 384 + j);
                float fa = acc[nt][half * 2 + 0] + fd.x + fs2.x;
                float fb = acc[nt][half * 2 + 1] + fd.y + fs2.y;
                float sa = acc[nt + 2][half * 2 + 0] + sd.x + ss2.x;
                float sb = acc[nt + 2][half * 2 + 1] + sd.y + ss2.y;
                float2 m = make_float2(sigm(fa) * softp(sa), sigm(fb) * softp(sb));
                red2(hout + (size_t)dN * 128 + j, m);
            }
        }
        buf ^= 1;
    }
}

// ---------------- small utility kernels ----------------
__global__ void copy_kernel(const float* __restrict__ a, float* __restrict__ b, int n4) {
    int i = blockIdx.x * blockDim.x + threadIdx.x;
    if (i < n4) ((float4*)b)[i] = ((const float4*)a)[i];
}
__global__ void zero_kernel(float* __restrict__ p, int n) {
    int i = blockIdx.x * blockDim.x + threadIdx.x;
    if (i < n) p[i] = 0.f;
}
__global__ void pool_kernel(const float* __restrict__ h, const int* __restrict__ batch,
                            float* __restrict__ g) {
    int idx = blockIdx.x * blockDim.x + threadIdx.x;
    if (idx >= NN * 32) return;
    int node = idx >> 5, qq = idx & 31;
    float4 v = ((const float4*)h)[idx];
    red4(g + (size_t)batch[node] * 128 + qq * 4, v);
}
__global__ void out_kernel(const float* __restrict__ gf, const float* __restrict__ oW,
                           const float* __restrict__ ob, float* __restrict__ out) {
    int gidx = blockIdx.x * 8 + (threadIdx.x >> 5);
    int lane = threadIdx.x & 31;
    if (gidx >= NG) return;
    float s = 0.f;
#pragma unroll
    for (int k = lane; k < 128; k += 32) s += gf[gidx * 128 + k] * oW[k];
#pragma unroll
    for (int o = 16; o; o >>= 1) s += __shfl_down_sync(0xffffffffu, s, o);
    if (lane == 0) out[gidx] = s + ob[0];
}

// ---------------- launch ----------------
extern "C" void kernel_launch(void* const* d_in, const int* in_sizes, int n_in,
                              void* d_out, int out_size) {
    (void)in_sizes; (void)n_in; (void)out_size;
    const float* x   = (const float*)d_in[0];
    const int*   ei  = (const int*)d_in[1];
    const float* ea  = (const float*)d_in[2];
    const int*   bat = (const int*)d_in[3];
    const float* Wf  = (const float*)d_in[4];
    const float* bf  = (const float*)d_in[5];
    const float* Ws  = (const float*)d_in[6];
    const float* bs  = (const float*)d_in[7];
    const float* m1W0 = (const float*)d_in[8],  *m1b0 = (const float*)d_in[9];
    const float* m1W1 = (const float*)d_in[10], *m1b1 = (const float*)d_in[11];
    const float* m1Wp = (const float*)d_in[12], *m1bp = (const float*)d_in[13];
    const float* m2W0 = (const float*)d_in[14], *m2b0 = (const float*)d_in[15];
    const float* m2W1 = (const float*)d_in[16], *m2b1 = (const float*)d_in[17];
    const float* m2Wp = (const float*)d_in[18], *m2bp = (const float*)d_in[19];
    const float* oW   = (const float*)d_in[20], *ob   = (const float*)d_in[21];
    float* out = (float*)d_out;

    float *pH0, *pH1, *pP, *pW, *pB, *pPool, *pT0g, *pT1g, *pGf;
    cudaGetSymbolAddress((void**)&pH0,  g_h0);
    cudaGetSymbolAddress((void**)&pH1,  g_h1);
    cudaGetSymbolAddress((void**)&pP,   g_P);
    cudaGetSymbolAddress((void**)&pW,   g_Wcat);
    cudaGetSymbolAddress((void**)&pB,   g_bcat);
    cudaGetSymbolAddress((void**)&pPool, g_pool);
    cudaGetSymbolAddress((void**)&pT0g, g_t0g);
    cudaGetSymbolAddress((void**)&pT1g, g_t1g);
    cudaGetSymbolAddress((void**)&pGf,  g_gfin);

    cudaFuncSetAttribute(hmma_gemm, cudaFuncAttributeMaxDynamicSharedMemorySize, HMMA_SMEM);
    cudaFuncSetAttribute(edge_hmma_kernel, cudaFuncAttributeMaxDynamicSharedMemorySize, EV9_SMEM);

    const int MB = (NN + 127) / 128;   // 391
    const int EGRID = 304;             // 2 per SM on 152 SMs

    // --- CGConv layer 0 ---
    pack_wcat<<<(512 * 128 + 255) / 256, 256>>>(Wf, Ws, bf, bs, pW, pB, 0);
    hmma_gemm<<<dim3(4, MB), 256, HMMA_SMEM>>>(x, pW, pB, nullptr, pP, NN, 512, 128, 0);
    copy_kernel<<<(NN * 32 + 255) / 256, 256>>>(x, pH0, NN * 32);
    edge_hmma_kernel<<<EGRID, 256, EV9_SMEM>>>(pP, ei, ea, Wf, Ws, 0, pH0);

    // --- CGConv layer 1 ---
    pack_wcat<<<(512 * 128 + 255) / 256, 256>>>(Wf, Ws, bf, bs, pW, pB, 1);
    hmma_gemm<<<dim3(4, MB), 256, HMMA_SMEM>>>(pH0, pW, pB, nullptr, pP, NN, 512, 128, 0);
    copy_kernel<<<(NN * 32 + 255) / 256, 256>>>(pH0, pH1, NN * 32);
    edge_hmma_kernel<<<EGRID, 256, EV9_SMEM>>>(pP, ei, ea, Wf, Ws, 1, pH1);

    // --- node MLP (residual) ---
    float* t0 = pP;
    float* t1 = pP + (size_t)NN * 256;
    hmma_gemm<<<dim3(2, MB), 256, HMMA_SMEM>>>(pH1, m1W0, m1b0, nullptr, t0, NN, 256, 128, 1);
    hmma_gemm<<<dim3(2, MB), 256, HMMA_SMEM>>>(t0, m1W1, m1b1, nullptr, t1, NN, 256, 256, 1);
    hmma_gemm<<<dim3(1, MB), 256, HMMA_SMEM>>>(t1, m1Wp, m1bp, pH1, pH0, NN, 128, 256, 0);

    // --- global add pool ---
    zero_kernel<<<(NG * 128 + 255) / 256, 256>>>(pPool, NG * 128);
    pool_kernel<<<(NN * 32 + 255) / 256, 256>>>(pH0, bat, pPool);

    // --- graph MLP (residual) + head ---
    sgemm_bt<<<dim3(2, 4), 256>>>(pPool, m2W0, m2b0, nullptr, pT0g, NG, 256, 128, 1);
    sgemm_bt<<<dim3(2, 4), 256>>>(pT0g, m2W1, m2b1, nullptr, pT1g, NG, 256, 256, 1);
    sgemm_bt<<<dim3(1, 4), 256>>>(pT1g, m2Wp, m2bp, pPool, pGf, NG, 128, 256, 0);
    out_kernel<<<64, 256>>>(pGf, oW, ob, out);
}

// round 14
// speedup vs baseline: 1.2265x; 1.2265x over previous
#include <cuda_runtime.h>
#include <cstdint>

#define NN 50000
#define NE 800000
#define NG 512

// ---------------- device scratch (static, no runtime alloc) ----------------
__device__ float g_h0[NN * 128];
__device__ float g_h1[NN * 128];
__device__ float g_P [NN * 512];
__device__ float g_Wcat[512 * 128];
__device__ float g_bcat[512];
__device__ float g_pool[NG * 128];
__device__ float g_t0g[NG * 256];
__device__ float g_t1g[NG * 256];
__device__ float g_gfin[NG * 128];

// ---------------- helpers ----------------
typedef unsigned long long u64;
__device__ __forceinline__ u64 pk2(float lo, float hi) {
    u64 r; asm("mov.b64 %0,{%1,%2};" : "=l"(r) : "f"(lo), "f"(hi)); return r;
}
__device__ __forceinline__ float2 up2(u64 v) {
    float2 r; asm("mov.b64 {%0,%1},%2;" : "=f"(r.x), "=f"(r.y) : "l"(v)); return r;
}
__device__ __forceinline__ u64 ffma2(u64 a, u64 b, u64 c) {
    u64 d; asm("fma.rn.f32x2 %0,%1,%2,%3;" : "=l"(d) : "l"(a), "l"(b), "l"(c)); return d;
}
union F4U { float4 f4; u64 u[2]; float f[4]; };

__device__ __forceinline__ void red4(float* addr, float4 v) {
    asm volatile("red.global.add.v4.f32 [%0], {%1,%2,%3,%4};"
                 :: "l"(addr), "f"(v.x), "f"(v.y), "f"(v.z), "f"(v.w) : "memory");
}
__device__ __forceinline__ void cpasync16(unsigned saddr, const void* gaddr) {
    asm volatile("cp.async.cg.shared.global [%0], [%1], 16;" :: "r"(saddr), "l"(gaddr));
}
__device__ __forceinline__ void cpcommit() { asm volatile("cp.async.commit_group;"); }
__device__ __forceinline__ void cpwait0()  { asm volatile("cp.async.wait_group 0;"); }

__device__ __forceinline__ float sigm(float x) { return 1.f / (1.f + __expf(-x)); }
__device__ __forceinline__ float softp(float x) {
    return fmaxf(x, 0.f) + __logf(1.f + __expf(-fabsf(x)));
}
__device__ __forceinline__ unsigned f2tf(float x) {
    unsigned r; asm("cvt.rna.tf32.f32 %0, %1;" : "=r"(r) : "f"(x)); return r;
}
__device__ __forceinline__ void mma_tf32_16n8k8(float* c, unsigned a0, unsigned a1,
                                                unsigned a2, unsigned a3,
                                                unsigned b0, unsigned b1) {
    asm volatile(
        "mma.sync.aligned.m16n8k8.row.col.f32.tf32.tf32.f32 "
        "{%0,%1,%2,%3}, {%4,%5,%6,%7}, {%8,%9}, {%0,%1,%2,%3};"
        : "+f"(c[0]), "+f"(c[1]), "+f"(c[2]), "+f"(c[3])
        : "r"(a0), "r"(a1), "r"(a2), "r"(a3), "r"(b0), "r"(b1));
}

// ---------------- pack concatenated projection weights ----------------
__global__ void pack_wcat(const float* __restrict__ Wf, const float* __restrict__ Ws,
                          const float* __restrict__ bf, const float* __restrict__ bs,
                          float* __restrict__ Wcat, float* __restrict__ bcat, int layer) {
    int idx = blockIdx.x * blockDim.x + threadIdx.x;
    if (idx < 512) {
        float b = 0.f;
        if (idx < 128) b = bf[layer * 128 + idx];
        else if (idx < 256) b = bs[layer * 128 + idx - 128];
        bcat[idx] = b;
    }
    if (idx >= 512 * 128) return;
    int n = idx >> 7, k = idx & 127;
    const float* W; int o, koff;
    if      (n < 128) { W = Wf; o = n;       koff = 0;   }
    else if (n < 256) { W = Ws; o = n - 128; koff = 0;   }
    else if (n < 384) { W = Wf; o = n - 256; koff = 128; }
    else              { W = Ws; o = n - 384; koff = 128; }
    Wcat[idx] = W[((size_t)(layer * 128 + o)) * 320 + koff + k];
}

// ---------------- HMMA tf32 GEMM (R10 win, unchanged) ----------------
#define GLDS 36
#define HMMA_SMEM (2 * 2 * 128 * GLDS * 4)   // 73728 bytes

__global__ void __launch_bounds__(256) hmma_gemm(
    const float* __restrict__ A, const float* __restrict__ B,
    const float* __restrict__ bias, const float* __restrict__ res,
    float* __restrict__ C, int M, int N, int K, int relu) {
    extern __shared__ float sm[];
    float* sA = sm;
    float* sB = sm + 2 * 128 * GLDS;
    unsigned saA = (unsigned)__cvta_generic_to_shared(sA);
    unsigned saB = (unsigned)__cvta_generic_to_shared(sB);

    int tid = threadIdx.x, wid = tid >> 5, lane = tid & 31;
    int warp_m = wid >> 2, warp_n = wid & 3;
    int r0 = lane >> 2, q = lane & 3;
    int m0 = blockIdx.y * 128, n0 = blockIdx.x * 128;

    auto stage = [&](int k0, int bb) {
#pragma unroll
        for (int t = 0; t < 4; t++) {
            int idx = tid + t * 256;
            int row = idx >> 3, c4 = idx & 7;
            int ar = m0 + row;
            if (ar < M)
                cpasync16(saA + (unsigned)(((bb * 128 + row) * GLDS + c4 * 4) * 4),
                          A + (size_t)ar * K + k0 + c4 * 4);
            cpasync16(saB + (unsigned)(((bb * 128 + row) * GLDS + c4 * 4) * 4),
                      B + (size_t)(n0 + row) * K + k0 + c4 * 4);
        }
    };

    float acc[4][4][4];
#pragma unroll
    for (int mt = 0; mt < 4; mt++)
#pragma unroll
        for (int nt = 0; nt < 4; nt++)
#pragma unroll
            for (int j = 0; j < 4; j++) acc[mt][nt][j] = 0.f;

    int nst = K >> 5;
    stage(0, 0); cpcommit();
    for (int s = 0; s < nst; s++) {
        cpwait0();
        __syncthreads();
        if (s + 1 < nst) { stage((s + 1) << 5, (s + 1) & 1); cpcommit(); }
        int bb = s & 1;
        const float* bA = sA + bb * 128 * GLDS;
        const float* bBp = sB + bb * 128 * GLDS;
#pragma unroll
        for (int ks = 0; ks < 4; ks++) {
            int k = ks * 8;
            unsigned af[4][4], bf4[4][2];
#pragma unroll
            for (int mt = 0; mt < 4; mt++) {
                const float* ap = bA + (warp_m * 64 + mt * 16 + r0) * GLDS + k + q;
                af[mt][0] = f2tf(ap[0]);
                af[mt][1] = f2tf(ap[8 * GLDS]);
                af[mt][2] = f2tf(ap[4]);
                af[mt][3] = f2tf(ap[8 * GLDS + 4]);
            }
#pragma unroll
            for (int nt = 0; nt < 4; nt++) {
                const float* bp = bBp + (warp_n * 32 + nt * 8 + r0) * GLDS + k + q;
                bf4[nt][0] = f2tf(bp[0]);
                bf4[nt][1] = f2tf(bp[4]);
            }
#pragma unroll
            for (int mt = 0; mt < 4; mt++)
#pragma unroll
                for (int nt = 0; nt < 4; nt++)
                    mma_tf32_16n8k8(acc[mt][nt], af[mt][0], af[mt][1], af[mt][2], af[mt][3],
                                    bf4[nt][0], bf4[nt][1]);
        }
        __syncthreads();
    }

#pragma unroll
    for (int mt = 0; mt < 4; mt++) {
#pragma unroll
        for (int half = 0; half < 2; half++) {
            int row = m0 + warp_m * 64 + mt * 16 + r0 + half * 8;
            if (row >= M) continue;
#pragma unroll
            for (int nt = 0; nt < 4; nt++) {
                int col = n0 + warp_n * 32 + nt * 8 + 2 * q;
                float v0 = acc[mt][nt][half * 2 + 0] + bias[col];
                float v1 = acc[mt][nt][half * 2 + 1] + bias[col + 1];
                if (res) {
                    float2 rv = *(const float2*)(res + (size_t)row * N + col);
                    v0 += rv.x; v1 += rv.y;
                }
                if (relu) { v0 = fmaxf(v0, 0.f); v1 = fmaxf(v1, 0.f); }
                *(float2*)(C + (size_t)row * N + col) = make_float2(v0, v1);
            }
        }
    }
}

// ---------------- SGEMM fp32 (graph-level, small) ----------------
__global__ void __launch_bounds__(256) sgemm_bt(
    const float* __restrict__ A, const float* __restrict__ B,
    const float* __restrict__ bias, const float* __restrict__ res,
    float* __restrict__ C, int M, int N, int K, int relu) {
    __shared__ float As[8][128];
    __shared__ float Bs[8][128];
    int tid = threadIdx.x;
    int m0 = blockIdx.y * 128;
    int n0 = blockIdx.x * 128;
    int tx = tid & 15, ty = tid >> 4;
    int lr = tid >> 1;
    int lk = (tid & 1) * 4;

    u64 acc[8][4];
#pragma unroll
    for (int i = 0; i < 8; i++)
#pragma unroll
        for (int j = 0; j < 4; j++) acc[i][j] = 0ull;

    for (int k0 = 0; k0 < K; k0 += 8) {
        float4 av = make_float4(0.f, 0.f, 0.f, 0.f);
        int arow = m0 + lr;
        if (arow < M) av = *(const float4*)(A + (size_t)arow * K + k0 + lk);
        As[lk + 0][lr] = av.x; As[lk + 1][lr] = av.y;
        As[lk + 2][lr] = av.z; As[lk + 3][lr] = av.w;
        float4 bv = *(const float4*)(B + (size_t)(n0 + lr) * K + k0 + lk);
        Bs[lk + 0][lr] = bv.x; Bs[lk + 1][lr] = bv.y;
        Bs[lk + 2][lr] = bv.z; Bs[lk + 3][lr] = bv.w;
        __syncthreads();
#pragma unroll
        for (int k = 0; k < 8; k++) {
            F4U b0, b1;
            b0.f4 = *(const float4*)&Bs[k][tx * 8];
            b1.f4 = *(const float4*)&Bs[k][tx * 8 + 4];
            float4 a0 = *(const float4*)&As[k][ty * 8];
            float4 a1 = *(const float4*)&As[k][ty * 8 + 4];
            float a[8] = {a0.x, a0.y, a0.z, a0.w, a1.x, a1.y, a1.z, a1.w};
#pragma unroll
            for (int i = 0; i < 8; i++) {
                u64 ai = pk2(a[i], a[i]);
                acc[i][0] = ffma2(ai, b0.u[0], acc[i][0]);
                acc[i][1] = ffma2(ai, b0.u[1], acc[i][1]);
                acc[i][2] = ffma2(ai, b1.u[0], acc[i][2]);
                acc[i][3] = ffma2(ai, b1.u[1], acc[i][3]);
            }
        }
        __syncthreads();
    }

#pragma unroll
    for (int i = 0; i < 8; i++) {
        int row = m0 + ty * 8 + i;
        if (row >= M) continue;
        int n = n0 + tx * 8;
        float o[8];
#pragma unroll
        for (int j2 = 0; j2 < 4; j2++) {
            float2 v = up2(acc[i][j2]);
            o[2 * j2] = v.x; o[2 * j2 + 1] = v.y;
        }
#pragma unroll
        for (int j = 0; j < 8; j++) {
            float v = o[j] + bias[n + j];
            if (res) v += res[(size_t)row * N + n + j];
            if (relu) v = fmaxf(v, 0.f);
            o[j] = v;
        }
        *(float4*)(C + (size_t)row * N + n)     = make_float4(o[0], o[1], o[2], o[3]);
        *(float4*)(C + (size_t)row * N + n + 4) = make_float4(o[4], o[5], o[6], o[7]);
    }
}

// ---------------- edge kernel v10: HMMA tf32 + two-phase coalesced epilogue ----------------
// Phase 1: MMA (as R10), STS accumulators -> sAcc[16 edges][264] (f 0..127 | s 128..255).
// Phase 2: warp w owns edges {2w, 2w+1}; 32 lanes span the 128 cols of ONE edge:
//          every global instruction touches ONE node -> 4 wavefronts instead of 8.
__global__ void __launch_bounds__(256, 2) edge_hmma_kernel(
    const float* __restrict__ Pall, const int* __restrict__ ei,
    const float* __restrict__ ea, const float* __restrict__ Wf,
    const float* __restrict__ Ws, int layer, float* __restrict__ hout) {
    __shared__ float sAcc[16 * 264];
    __shared__ float sEa[2][16][68];
    __shared__ int sIdx[2][32];

    int tid = threadIdx.x, w = tid >> 5, lane = tid & 31;
    int q = lane & 3, r0 = lane >> 2;

    // persistent B fragments (register-resident, R10 layout)
    unsigned bfr[4][8][2];
#pragma unroll
    for (int nt = 0; nt < 4; nt++) {
        int j = w * 16 + (nt & 1) * 8 + r0;
        const float* Wp = ((nt < 2) ? Wf : Ws) + (size_t)(layer * 128 + j) * 320 + 256;
#pragma unroll
        for (int ks = 0; ks < 8; ks++) {
            bfr[nt][ks][0] = f2tf(__ldg(Wp + ks * 8 + q));
            bfr[nt][ks][1] = f2tf(__ldg(Wp + ks * 8 + q + 4));
        }
    }

    const int NT = NE / 16;
    int nbs = gridDim.x;
    int tile = blockIdx.x;

    auto stage = [&](int t, int bb) {
        int e0 = t << 4;
        int row = tid >> 4, ch = tid & 15;
        unsigned daddr = (unsigned)__cvta_generic_to_shared(&sEa[bb][row][0]) + ch * 16;
        cpasync16(daddr, ea + (size_t)(e0 + row) * 64 + ch * 4);
        if (tid < 32) sIdx[bb][tid] = __ldg(ei + (tid < 16 ? 0 : NE) + e0 + (tid & 15));
    };

    if (tile < NT) stage(tile, 0);
    cpcommit();

    int buf = 0;
    for (; tile < NT; tile += nbs) {
        cpwait0();
        __syncthreads();                 // EA(tile) visible; prev phase-2 done (sAcc free)
        int nxt = tile + nbs;
        if (nxt < NT) stage(nxt, buf ^ 1);
        cpcommit();

        // ---- phase 1: tensor-core GEMM, 16 edges x 64 cols per warp ----
        float acc[4][4];
#pragma unroll
        for (int nt = 0; nt < 4; nt++)
#pragma unroll
            for (int j = 0; j < 4; j++) acc[nt][j] = 0.f;

#pragma unroll
        for (int ks = 0; ks < 8; ks++) {
            unsigned a0 = f2tf(sEa[buf][r0][ks * 8 + q]);
            unsigned a1 = f2tf(sEa[buf][r0 + 8][ks * 8 + q]);
            unsigned a2 = f2tf(sEa[buf][r0][ks * 8 + q + 4]);
            unsigned a3 = f2tf(sEa[buf][r0 + 8][ks * 8 + q + 4]);
#pragma unroll
            for (int nt = 0; nt < 4; nt++)
                mma_tf32_16n8k8(acc[nt], a0, a1, a2, a3, bfr[nt][ks][0], bfr[nt][ks][1]);
        }

        // STS accumulators into edge-major tile
#pragma unroll
        for (int nt = 0; nt < 4; nt++) {
            int base = (nt < 2) ? 0 : 128;
            int c = w * 16 + (nt & 1) * 8 + 2 * q;
#pragma unroll
            for (int half = 0; half < 2; half++) {
                int row = r0 + half * 8;
                *(float2*)&sAcc[row * 264 + base + c] =
                    make_float2(acc[nt][half * 2], acc[nt][half * 2 + 1]);
            }
        }
        __syncthreads();

        // ---- phase 2: one edge per warp-pass, fully coalesced ----
#pragma unroll
        for (int t = 0; t < 2; t++) {
            int e = w * 2 + t;
            int sN = sIdx[buf][e], dN = sIdx[buf][16 + e];
            int c = lane * 4;
            float4 f4 = *(float4*)&sAcc[e * 264 + c];
            float4 s4 = *(float4*)&sAcc[e * 264 + 128 + c];
            const float* pd = Pall + (size_t)dN * 512;
            const float* ps = Pall + (size_t)sN * 512;
            float4 fd = *(const float4*)(pd + c);
            float4 sd = *(const float4*)(pd + 128 + c);
            float4 fs = *(const float4*)(ps + 256 + c);
            float4 ss = *(const float4*)(ps + 384 + c);
            float4 m;
            m.x = sigm(f4.x + fd.x + fs.x) * softp(s4.x + sd.x + ss.x);
            m.y = sigm(f4.y + fd.y + fs.y) * softp(s4.y + sd.y + ss.y);
            m.z = sigm(f4.z + fd.z + fs.z) * softp(s4.z + sd.z + ss.z);
            m.w = sigm(f4.w + fd.w + fs.w) * softp(s4.w + sd.w + ss.w);
            red4(hout + (size_t)dN * 128 + c, m);
        }
        buf ^= 1;
    }
}

// ---------------- small utility kernels ----------------
__global__ void copy_kernel(const float* __restrict__ a, float* __restrict__ b, int n4) {
    int i = blockIdx.x * blockDim.x + threadIdx.x;
    if (i < n4) ((float4*)b)[i] = ((const float4*)a)[i];
}
__global__ void zero_kernel(float* __restrict__ p, int n) {
    int i = blockIdx.x * blockDim.x + threadIdx.x;
    if (i < n) p[i] = 0.f;
}
__global__ void pool_kernel(const float* __restrict__ h, const int* __restrict__ batch,
                            float* __restrict__ g) {
    int idx = blockIdx.x * blockDim.x + threadIdx.x;
    if (idx >= NN * 32) return;
    int node = idx >> 5, qq = idx & 31;
    float4 v = ((const float4*)h)[idx];
    red4(g + (size_t)batch[node] * 128 + qq * 4, v);
}
__global__ void out_kernel(const float* __restrict__ gf, const float* __restrict__ oW,
                           const float* __restrict__ ob, float* __restrict__ out) {
    int gidx = blockIdx.x * 8 + (threadIdx.x >> 5);
    int lane = threadIdx.x & 31;
    if (gidx >= NG) return;
    float s = 0.f;
#pragma unroll
    for (int k = lane; k < 128; k += 32) s += gf[gidx * 128 + k] * oW[k];
#pragma unroll
    for (int o = 16; o; o >>= 1) s += __shfl_down_sync(0xffffffffu, s, o);
    if (lane == 0) out[gidx] = s + ob[0];
}

// ---------------- launch ----------------
extern "C" void kernel_launch(void* const* d_in, const int* in_sizes, int n_in,
                              void* d_out, int out_size) {
    (void)in_sizes; (void)n_in; (void)out_size;
    const float* x   = (const float*)d_in[0];
    const int*   ei  = (const int*)d_in[1];
    const float* ea  = (const float*)d_in[2];
    const int*   bat = (const int*)d_in[3];
    const float* Wf  = (const float*)d_in[4];
    const float* bf  = (const float*)d_in[5];
    const float* Ws  = (const float*)d_in[6];
    const float* bs  = (const float*)d_in[7];
    const float* m1W0 = (const float*)d_in[8],  *m1b0 = (const float*)d_in[9];
    const float* m1W1 = (const float*)d_in[10], *m1b1 = (const float*)d_in[11];
    const float* m1Wp = (const float*)d_in[12], *m1bp = (const float*)d_in[13];
    const float* m2W0 = (const float*)d_in[14], *m2b0 = (const float*)d_in[15];
    const float* m2W1 = (const float*)d_in[16], *m2b1 = (const float*)d_in[17];
    const float* m2Wp = (const float*)d_in[18], *m2bp = (const float*)d_in[19];
    const float* oW   = (const float*)d_in[20], *ob   = (const float*)d_in[21];
    float* out = (float*)d_out;

    float *pH0, *pH1, *pP, *pW, *pB, *pPool, *pT0g, *pT1g, *pGf;
    cudaGetSymbolAddress((void**)&pH0,  g_h0);
    cudaGetSymbolAddress((void**)&pH1,  g_h1);
    cudaGetSymbolAddress((void**)&pP,   g_P);
    cudaGetSymbolAddress((void**)&pW,   g_Wcat);
    cudaGetSymbolAddress((void**)&pB,   g_bcat);
    cudaGetSymbolAddress((void**)&pPool, g_pool);
    cudaGetSymbolAddress((void**)&pT0g, g_t0g);
    cudaGetSymbolAddress((void**)&pT1g, g_t1g);
    cudaGetSymbolAddress((void**)&pGf,  g_gfin);

    cudaFuncSetAttribute(hmma_gemm, cudaFuncAttributeMaxDynamicSharedMemorySize, HMMA_SMEM);

    const int MB = (NN + 127) / 128;   // 391
    const int EGRID = 304;             // 2 per SM on 152 SMs

    // --- CGConv layer 0 ---
    pack_wcat<<<(512 * 128 + 255) / 256, 256>>>(Wf, Ws, bf, bs, pW, pB, 0);
    hmma_gemm<<<dim3(4, MB), 256, HMMA_SMEM>>>(x, pW, pB, nullptr, pP, NN, 512, 128, 0);
    copy_kernel<<<(NN * 32 + 255) / 256, 256>>>(x, pH0, NN * 32);
    edge_hmma_kernel<<<EGRID, 256>>>(pP, ei, ea, Wf, Ws, 0, pH0);

    // --- CGConv layer 1 ---
    pack_wcat<<<(512 * 128 + 255) / 256, 256>>>(Wf, Ws, bf, bs, pW, pB, 1);
    hmma_gemm<<<dim3(4, MB), 256, HMMA_SMEM>>>(pH0, pW, pB, nullptr, pP, NN, 512, 128, 0);
    copy_kernel<<<(NN * 32 + 255) / 256, 256>>>(pH0, pH1, NN * 32);
    edge_hmma_kernel<<<EGRID, 256>>>(pP, ei, ea, Wf, Ws, 1, pH1);

    // --- node MLP (residual) ---
    float* t0 = pP;
    float* t1 = pP + (size_t)NN * 256;
    hmma_gemm<<<dim3(2, MB), 256, HMMA_SMEM>>>(pH1, m1W0, m1b0, nullptr, t0, NN, 256, 128, 1);
    hmma_gemm<<<dim3(2, MB), 256, HMMA_SMEM>>>(t0, m1W1, m1b1, nullptr, t1, NN, 256, 256, 1);
    hmma_gemm<<<dim3(1, MB), 256, HMMA_SMEM>>>(t1, m1Wp, m1bp, pH1, pH0, NN, 128, 256, 0);

    // --- global add pool ---
    zero_kernel<<<(NG * 128 + 255) / 256, 256>>>(pPool, NG * 128);
    pool_kernel<<<(NN * 32 + 255) / 256, 256>>>(pH0, bat, pPool);

    // --- graph MLP (residual) + head ---
    sgemm_bt<<<dim3(2, 4), 256>>>(pPool, m2W0, m2b0, nullptr, pT0g, NG, 256, 128, 1);
    sgemm_bt<<<dim3(2, 4), 256>>>(pT0g, m2W1, m2b1, nullptr, pT1g, NG, 256, 256, 1);
    sgemm_bt<<<dim3(1, 4), 256>>>(pT1g, m2Wp, m2bp, pPool, pGf, NG, 128, 256, 0);
    out_kernel<<<64, 256>>>(pGf, oW, ob, out);
}

// round 15
// speedup vs baseline: 1.3158x; 1.0728x over previous
#include <cuda_runtime.h>
#include <cuda_fp16.h>
#include <cstdint>

#define NN 50000
#define NE 800000
#define NG 512

// ---------------- device scratch (static, no runtime alloc) ----------------
__device__ float  g_h0[NN * 128];
__device__ float  g_h1[NN * 128];
__device__ __half g_Ph[NN * 512];     // node projections in fp16 (51MB, L2-resident)
__device__ float  g_t0[NN * 256];
__device__ float  g_t1[NN * 256];
__device__ float  g_Wcat[512 * 128];
__device__ float  g_bcat[512];
__device__ float  g_pool[NG * 128];
__device__ float  g_t0g[NG * 256];
__device__ float  g_t1g[NG * 256];
__device__ float  g_gfin[NG * 128];

// ---------------- helpers ----------------
typedef unsigned long long u64;
__device__ __forceinline__ u64 pk2(float lo, float hi) {
    u64 r; asm("mov.b64 %0,{%1,%2};" : "=l"(r) : "f"(lo), "f"(hi)); return r;
}
__device__ __forceinline__ float2 up2(u64 v) {
    float2 r; asm("mov.b64 {%0,%1},%2;" : "=f"(r.x), "=f"(r.y) : "l"(v)); return r;
}
__device__ __forceinline__ u64 ffma2(u64 a, u64 b, u64 c) {
    u64 d; asm("fma.rn.f32x2 %0,%1,%2,%3;" : "=l"(d) : "l"(a), "l"(b), "l"(c)); return d;
}
union F4U { float4 f4; u64 u[2]; float f[4]; };

__device__ __forceinline__ void red4(float* addr, float4 v) {
    asm volatile("red.global.add.v4.f32 [%0], {%1,%2,%3,%4};"
                 :: "l"(addr), "f"(v.x), "f"(v.y), "f"(v.z), "f"(v.w) : "memory");
}
__device__ __forceinline__ void cpasync16(unsigned saddr, const void* gaddr) {
    asm volatile("cp.async.cg.shared.global [%0], [%1], 16;" :: "r"(saddr), "l"(gaddr));
}
__device__ __forceinline__ void cpcommit() { asm volatile("cp.async.commit_group;"); }
__device__ __forceinline__ void cpwait0()  { asm volatile("cp.async.wait_group 0;"); }

__device__ __forceinline__ float sigm(float x) { return 1.f / (1.f + __expf(-x)); }
__device__ __forceinline__ float softp(float x) {
    return fmaxf(x, 0.f) + __logf(1.f + __expf(-fabsf(x)));
}
__device__ __forceinline__ unsigned f2tf(float x) {
    unsigned r; asm("cvt.rna.tf32.f32 %0, %1;" : "=r"(r) : "f"(x)); return r;
}
__device__ __forceinline__ void mma_tf32_16n8k8(float* c, unsigned a0, unsigned a1,
                                                unsigned a2, unsigned a3,
                                                unsigned b0, unsigned b1) {
    asm volatile(
        "mma.sync.aligned.m16n8k8.row.col.f32.tf32.tf32.f32 "
        "{%0,%1,%2,%3}, {%4,%5,%6,%7}, {%8,%9}, {%0,%1,%2,%3};"
        : "+f"(c[0]), "+f"(c[1]), "+f"(c[2]), "+f"(c[3])
        : "r"(a0), "r"(a1), "r"(a2), "r"(a3), "r"(b0), "r"(b1));
}

// ---------------- pack concatenated projection weights ----------------
__global__ void pack_wcat(const float* __restrict__ Wf, const float* __restrict__ Ws,
                          const float* __restrict__ bf, const float* __restrict__ bs,
                          float* __restrict__ Wcat, float* __restrict__ bcat, int layer) {
    int idx = blockIdx.x * blockDim.x + threadIdx.x;
    if (idx < 512) {
        float b = 0.f;
        if (idx < 128) b = bf[layer * 128 + idx];
        else if (idx < 256) b = bs[layer * 128 + idx - 128];
        bcat[idx] = b;
    }
    if (idx >= 512 * 128) return;
    int n = idx >> 7, k = idx & 127;
    const float* W; int o, koff;
    if      (n < 128) { W = Wf; o = n;       koff = 0;   }
    else if (n < 256) { W = Ws; o = n - 128; koff = 0;   }
    else if (n < 384) { W = Wf; o = n - 256; koff = 128; }
    else              { W = Ws; o = n - 384; koff = 128; }
    Wcat[idx] = W[((size_t)(layer * 128 + o)) * 320 + koff + k];
}

// ---------------- HMMA tf32 GEMM, f32 output (R10 win, unchanged) ----------------
#define GLDS 36
#define HMMA_SMEM (2 * 2 * 128 * GLDS * 4)   // 73728 bytes

__global__ void __launch_bounds__(256) hmma_gemm(
    const float* __restrict__ A, const float* __restrict__ B,
    const float* __restrict__ bias, const float* __restrict__ res,
    float* __restrict__ C, int M, int N, int K, int relu) {
    extern __shared__ float sm[];
    float* sA = sm;
    float* sB = sm + 2 * 128 * GLDS;
    unsigned saA = (unsigned)__cvta_generic_to_shared(sA);
    unsigned saB = (unsigned)__cvta_generic_to_shared(sB);

    int tid = threadIdx.x, wid = tid >> 5, lane = tid & 31;
    int warp_m = wid >> 2, warp_n = wid & 3;
    int r0 = lane >> 2, q = lane & 3;
    int m0 = blockIdx.y * 128, n0 = blockIdx.x * 128;

    auto stage = [&](int k0, int bb) {
#pragma unroll
        for (int t = 0; t < 4; t++) {
            int idx = tid + t * 256;
            int row = idx >> 3, c4 = idx & 7;
            int ar = m0 + row;
            if (ar < M)
                cpasync16(saA + (unsigned)(((bb * 128 + row) * GLDS + c4 * 4) * 4),
                          A + (size_t)ar * K + k0 + c4 * 4);
            cpasync16(saB + (unsigned)(((bb * 128 + row) * GLDS + c4 * 4) * 4),
                      B + (size_t)(n0 + row) * K + k0 + c4 * 4);
        }
    };

    float acc[4][4][4];
#pragma unroll
    for (int mt = 0; mt < 4; mt++)
#pragma unroll
        for (int nt = 0; nt < 4; nt++)
#pragma unroll
            for (int j = 0; j < 4; j++) acc[mt][nt][j] = 0.f;

    int nst = K >> 5;
    stage(0, 0); cpcommit();
    for (int s = 0; s < nst; s++) {
        cpwait0();
        __syncthreads();
        if (s + 1 < nst) { stage((s + 1) << 5, (s + 1) & 1); cpcommit(); }
        int bb = s & 1;
        const float* bA = sA + bb * 128 * GLDS;
        const float* bBp = sB + bb * 128 * GLDS;
#pragma unroll
        for (int ks = 0; ks < 4; ks++) {
            int k = ks * 8;
            unsigned af[4][4], bf4[4][2];
#pragma unroll
            for (int mt = 0; mt < 4; mt++) {
                const float* ap = bA + (warp_m * 64 + mt * 16 + r0) * GLDS + k + q;
                af[mt][0] = f2tf(ap[0]);
                af[mt][1] = f2tf(ap[8 * GLDS]);
                af[mt][2] = f2tf(ap[4]);
                af[mt][3] = f2tf(ap[8 * GLDS + 4]);
            }
#pragma unroll
            for (int nt = 0; nt < 4; nt++) {
                const float* bp = bBp + (warp_n * 32 + nt * 8 + r0) * GLDS + k + q;
                bf4[nt][0] = f2tf(bp[0]);
                bf4[nt][1] = f2tf(bp[4]);
            }
#pragma unroll
            for (int mt = 0; mt < 4; mt++)
#pragma unroll
                for (int nt = 0; nt < 4; nt++)
                    mma_tf32_16n8k8(acc[mt][nt], af[mt][0], af[mt][1], af[mt][2], af[mt][3],
                                    bf4[nt][0], bf4[nt][1]);
        }
        __syncthreads();
    }

#pragma unroll
    for (int mt = 0; mt < 4; mt++) {
#pragma unroll
        for (int half = 0; half < 2; half++) {
            int row = m0 + warp_m * 64 + mt * 16 + r0 + half * 8;
            if (row >= M) continue;
#pragma unroll
            for (int nt = 0; nt < 4; nt++) {
                int col = n0 + warp_n * 32 + nt * 8 + 2 * q;
                float v0 = acc[mt][nt][half * 2 + 0] + bias[col];
                float v1 = acc[mt][nt][half * 2 + 1] + bias[col + 1];
                if (res) {
                    float2 rv = *(const float2*)(res + (size_t)row * N + col);
                    v0 += rv.x; v1 += rv.y;
                }
                if (relu) { v0 = fmaxf(v0, 0.f); v1 = fmaxf(v1, 0.f); }
                *(float2*)(C + (size_t)row * N + col) = make_float2(v0, v1);
            }
        }
    }
}

// ---------------- HMMA tf32 GEMM, fp16 output (P producer) ----------------
__global__ void __launch_bounds__(256) hmma_gemm_half(
    const float* __restrict__ A, const float* __restrict__ B,
    const float* __restrict__ bias, __half* __restrict__ C,
    int M, int N, int K) {
    extern __shared__ float sm[];
    float* sA = sm;
    float* sB = sm + 2 * 128 * GLDS;
    unsigned saA = (unsigned)__cvta_generic_to_shared(sA);
    unsigned saB = (unsigned)__cvta_generic_to_shared(sB);

    int tid = threadIdx.x, wid = tid >> 5, lane = tid & 31;
    int warp_m = wid >> 2, warp_n = wid & 3;
    int r0 = lane >> 2, q = lane & 3;
    int m0 = blockIdx.y * 128, n0 = blockIdx.x * 128;

    auto stage = [&](int k0, int bb) {
#pragma unroll
        for (int t = 0; t < 4; t++) {
            int idx = tid + t * 256;
            int row = idx >> 3, c4 = idx & 7;
            int ar = m0 + row;
            if (ar < M)
                cpasync16(saA + (unsigned)(((bb * 128 + row) * GLDS + c4 * 4) * 4),
                          A + (size_t)ar * K + k0 + c4 * 4);
            cpasync16(saB + (unsigned)(((bb * 128 + row) * GLDS + c4 * 4) * 4),
                      B + (size_t)(n0 + row) * K + k0 + c4 * 4);
        }
    };

    float acc[4][4][4];
#pragma unroll
    for (int mt = 0; mt < 4; mt++)
#pragma unroll
        for (int nt = 0; nt < 4; nt++)
#pragma unroll
            for (int j = 0; j < 4; j++) acc[mt][nt][j] = 0.f;

    int nst = K >> 5;
    stage(0, 0); cpcommit();
    for (int s = 0; s < nst; s++) {
        cpwait0();
        __syncthreads();
        if (s + 1 < nst) { stage((s + 1) << 5, (s + 1) & 1); cpcommit(); }
        int bb = s & 1;
        const float* bA = sA + bb * 128 * GLDS;
        const float* bBp = sB + bb * 128 * GLDS;
#pragma unroll
        for (int ks = 0; ks < 4; ks++) {
            int k = ks * 8;
            unsigned af[4][4], bf4[4][2];
#pragma unroll
            for (int mt = 0; mt < 4; mt++) {
                const float* ap = bA + (warp_m * 64 + mt * 16 + r0) * GLDS + k + q;
                af[mt][0] = f2tf(ap[0]);
                af[mt][1] = f2tf(ap[8 * GLDS]);
                af[mt][2] = f2tf(ap[4]);
                af[mt][3] = f2tf(ap[8 * GLDS + 4]);
            }
#pragma unroll
            for (int nt = 0; nt < 4; nt++) {
                const float* bp = bBp + (warp_n * 32 + nt * 8 + r0) * GLDS + k + q;
                bf4[nt][0] = f2tf(bp[0]);
                bf4[nt][1] = f2tf(bp[4]);
            }
#pragma unroll
            for (int mt = 0; mt < 4; mt++)
#pragma unroll
                for (int nt = 0; nt < 4; nt++)
                    mma_tf32_16n8k8(acc[mt][nt], af[mt][0], af[mt][1], af[mt][2], af[mt][3],
                                    bf4[nt][0], bf4[nt][1]);
        }
        __syncthreads();
    }

#pragma unroll
    for (int mt = 0; mt < 4; mt++) {
#pragma unroll
        for (int half = 0; half < 2; half++) {
            int row = m0 + warp_m * 64 + mt * 16 + r0 + half * 8;
            if (row >= M) continue;
#pragma unroll
            for (int nt = 0; nt < 4; nt++) {
                int col = n0 + warp_n * 32 + nt * 8 + 2 * q;
                float v0 = acc[mt][nt][half * 2 + 0] + bias[col];
                float v1 = acc[mt][nt][half * 2 + 1] + bias[col + 1];
                *(__half2*)(C + (size_t)row * N + col) = __floats2half2_rn(v0, v1);
            }
        }
    }
}

// ---------------- SGEMM fp32 (graph-level, small) ----------------
__global__ void __launch_bounds__(256) sgemm_bt(
    const float* __restrict__ A, const float* __restrict__ B,
    const float* __restrict__ bias, const float* __restrict__ res,
    float* __restrict__ C, int M, int N, int K, int relu) {
    __shared__ float As[8][128];
    __shared__ float Bs[8][128];
    int tid = threadIdx.x;
    int m0 = blockIdx.y * 128;
    int n0 = blockIdx.x * 128;
    int tx = tid & 15, ty = tid >> 4;
    int lr = tid >> 1;
    int lk = (tid & 1) * 4;

    u64 acc[8][4];
#pragma unroll
    for (int i = 0; i < 8; i++)
#pragma unroll
        for (int j = 0; j < 4; j++) acc[i][j] = 0ull;

    for (int k0 = 0; k0 < K; k0 += 8) {
        float4 av = make_float4(0.f, 0.f, 0.f, 0.f);
        int arow = m0 + lr;
        if (arow < M) av = *(const float4*)(A + (size_t)arow * K + k0 + lk);
        As[lk + 0][lr] = av.x; As[lk + 1][lr] = av.y;
        As[lk + 2][lr] = av.z; As[lk + 3][lr] = av.w;
        float4 bv = *(const float4*)(B + (size_t)(n0 + lr) * K + k0 + lk);
        Bs[lk + 0][lr] = bv.x; Bs[lk + 1][lr] = bv.y;
        Bs[lk + 2][lr] = bv.z; Bs[lk + 3][lr] = bv.w;
        __syncthreads();
#pragma unroll
        for (int k = 0; k < 8; k++) {
            F4U b0, b1;
            b0.f4 = *(const float4*)&Bs[k][tx * 8];
            b1.f4 = *(const float4*)&Bs[k][tx * 8 + 4];
            float4 a0 = *(const float4*)&As[k][ty * 8];
            float4 a1 = *(const float4*)&As[k][ty * 8 + 4];
            float a[8] = {a0.x, a0.y, a0.z, a0.w, a1.x, a1.y, a1.z, a1.w};
#pragma unroll
            for (int i = 0; i < 8; i++) {
                u64 ai = pk2(a[i], a[i]);
                acc[i][0] = ffma2(ai, b0.u[0], acc[i][0]);
                acc[i][1] = ffma2(ai, b0.u[1], acc[i][1]);
                acc[i][2] = ffma2(ai, b1.u[0], acc[i][2]);
                acc[i][3] = ffma2(ai, b1.u[1], acc[i][3]);
            }
        }
        __syncthreads();
    }

#pragma unroll
    for (int i = 0; i < 8; i++) {
        int row = m0 + ty * 8 + i;
        if (row >= M) continue;
        int n = n0 + tx * 8;
        float o[8];
#pragma unroll
        for (int j2 = 0; j2 < 4; j2++) {
            float2 v = up2(acc[i][j2]);
            o[2 * j2] = v.x; o[2 * j2 + 1] = v.y;
        }
#pragma unroll
        for (int j = 0; j < 8; j++) {
            float v = o[j] + bias[n + j];
            if (res) v += res[(size_t)row * N + n + j];
            if (relu) v = fmaxf(v, 0.f);
            o[j] = v;
        }
        *(float4*)(C + (size_t)row * N + n)     = make_float4(o[0], o[1], o[2], o[3]);
        *(float4*)(C + (size_t)row * N + n + 4) = make_float4(o[4], o[5], o[6], o[7]);
    }
}

// ---------------- edge kernel v11: two-phase epilogue + fp16 P gathers ----------------
__global__ void __launch_bounds__(256, 2) edge_hmma_kernel(
    const __half* __restrict__ Pall, const int* __restrict__ ei,
    const float* __restrict__ ea, const float* __restrict__ Wf,
    const float* __restrict__ Ws, int layer, float* __restrict__ hout) {
    __shared__ float sAcc[16 * 264];
    __shared__ float sEa[2][16][68];
    __shared__ int sIdx[2][32];

    int tid = threadIdx.x, w = tid >> 5, lane = tid & 31;
    int q = lane & 3, r0 = lane >> 2;

    // persistent B fragments (register-resident, R10 layout)
    unsigned bfr[4][8][2];
#pragma unroll
    for (int nt = 0; nt < 4; nt++) {
        int j = w * 16 + (nt & 1) * 8 + r0;
        const float* Wp = ((nt < 2) ? Wf : Ws) + (size_t)(layer * 128 + j) * 320 + 256;
#pragma unroll
        for (int ks = 0; ks < 8; ks++) {
            bfr[nt][ks][0] = f2tf(__ldg(Wp + ks * 8 + q));
            bfr[nt][ks][1] = f2tf(__ldg(Wp + ks * 8 + q + 4));
        }
    }

    const int NT = NE / 16;
    int nbs = gridDim.x;
    int tile = blockIdx.x;

    auto stage = [&](int t, int bb) {
        int e0 = t << 4;
        int row = tid >> 4, ch = tid & 15;
        unsigned daddr = (unsigned)__cvta_generic_to_shared(&sEa[bb][row][0]) + ch * 16;
        cpasync16(daddr, ea + (size_t)(e0 + row) * 64 + ch * 4);
        if (tid < 32) sIdx[bb][tid] = __ldg(ei + (tid < 16 ? 0 : NE) + e0 + (tid & 15));
    };

    if (tile < NT) stage(tile, 0);
    cpcommit();

    int buf = 0;
    for (; tile < NT; tile += nbs) {
        cpwait0();
        __syncthreads();                 // EA(tile) visible; prev phase-2 done
        int nxt = tile + nbs;
        if (nxt < NT) stage(nxt, buf ^ 1);
        cpcommit();

        // ---- phase 1: tensor-core GEMM ----
        float acc[4][4];
#pragma unroll
        for (int nt = 0; nt < 4; nt++)
#pragma unroll
            for (int j = 0; j < 4; j++) acc[nt][j] = 0.f;

#pragma unroll
        for (int ks = 0; ks < 8; ks++) {
            unsigned a0 = f2tf(sEa[buf][r0][ks * 8 + q]);
            unsigned a1 = f2tf(sEa[buf][r0 + 8][ks * 8 + q]);
            unsigned a2 = f2tf(sEa[buf][r0][ks * 8 + q + 4]);
            unsigned a3 = f2tf(sEa[buf][r0 + 8][ks * 8 + q + 4]);
#pragma unroll
            for (int nt = 0; nt < 4; nt++)
                mma_tf32_16n8k8(acc[nt], a0, a1, a2, a3, bfr[nt][ks][0], bfr[nt][ks][1]);
        }

#pragma unroll
        for (int nt = 0; nt < 4; nt++) {
            int base = (nt < 2) ? 0 : 128;
            int c = w * 16 + (nt & 1) * 8 + 2 * q;
#pragma unroll
            for (int half = 0; half < 2; half++) {
                int row = r0 + half * 8;
                *(float2*)&sAcc[row * 264 + base + c] =
                    make_float2(acc[nt][half * 2], acc[nt][half * 2 + 1]);
            }
        }
        __syncthreads();

        // ---- phase 2: one edge per warp-pass, coalesced fp16 gathers ----
#pragma unroll
        for (int t = 0; t < 2; t++) {
            int e = w * 2 + t;
            int sN = sIdx[buf][e], dN = sIdx[buf][16 + e];
            int c = lane * 4;
            float4 f4 = *(float4*)&sAcc[e * 264 + c];
            float4 s4 = *(float4*)&sAcc[e * 264 + 128 + c];
            const __half* pd = Pall + (size_t)dN * 512;
            const __half* ps = Pall + (size_t)sN * 512;
            uint2 vfd = *(const uint2*)(pd + c);
            uint2 vsd = *(const uint2*)(pd + 128 + c);
            uint2 vfs = *(const uint2*)(ps + 256 + c);
            uint2 vss = *(const uint2*)(ps + 384 + c);
            float2 fd0 = __half22float2(*(__half2*)&vfd.x), fd1 = __half22float2(*(__half2*)&vfd.y);
            float2 sd0 = __half22float2(*(__half2*)&vsd.x), sd1 = __half22float2(*(__half2*)&vsd.y);
            float2 fs0 = __half22float2(*(__half2*)&vfs.x), fs1 = __half22float2(*(__half2*)&vfs.y);
            float2 ss0 = __half22float2(*(__half2*)&vss.x), ss1 = __half22float2(*(__half2*)&vss.y);
            float4 m;
            m.x = sigm(f4.x + fd0.x + fs0.x) * softp(s4.x + sd0.x + ss0.x);
            m.y = sigm(f4.y + fd0.y + fs0.y) * softp(s4.y + sd0.y + ss0.y);
            m.z = sigm(f4.z + fd1.x + fs1.x) * softp(s4.z + sd1.x + ss1.x);
            m.w = sigm(f4.w + fd1.y + fs1.y) * softp(s4.w + sd1.y + ss1.y);
            red4(hout + (size_t)dN * 128 + c, m);
        }
        buf ^= 1;
    }
}

// ---------------- small utility kernels ----------------
__global__ void copy_kernel(const float* __restrict__ a, float* __restrict__ b, int n4) {
    int i = blockIdx.x * blockDim.x + threadIdx.x;
    if (i < n4) ((float4*)b)[i] = ((const float4*)a)[i];
}
__global__ void zero_kernel(float* __restrict__ p, int n) {
    int i = blockIdx.x * blockDim.x + threadIdx.x;
    if (i < n) p[i] = 0.f;
}
__global__ void pool_kernel(const float* __restrict__ h, const int* __restrict__ batch,
                            float* __restrict__ g) {
    int idx = blockIdx.x * blockDim.x + threadIdx.x;
    if (idx >= NN * 32) return;
    int node = idx >> 5, qq = idx & 31;
    float4 v = ((const float4*)h)[idx];
    red4(g + (size_t)batch[node] * 128 + qq * 4, v);
}
__global__ void out_kernel(const float* __restrict__ gf, const float* __restrict__ oW,
                           const float* __restrict__ ob, float* __restrict__ out) {
    int gidx = blockIdx.x * 8 + (threadIdx.x >> 5);
    int lane = threadIdx.x & 31;
    if (gidx >= NG) return;
    float s = 0.f;
#pragma unroll
    for (int k = lane; k < 128; k += 32) s += gf[gidx * 128 + k] * oW[k];
#pragma unroll
    for (int o = 16; o; o >>= 1) s += __shfl_down_sync(0xffffffffu, s, o);
    if (lane == 0) out[gidx] = s + ob[0];
}

// ---------------- launch ----------------
extern "C" void kernel_launch(void* const* d_in, const int* in_sizes, int n_in,
                              void* d_out, int out_size) {
    (void)in_sizes; (void)n_in; (void)out_size;
    const float* x   = (const float*)d_in[0];
    const int*   ei  = (const int*)d_in[1];
    const float* ea  = (const float*)d_in[2];
    const int*   bat = (const int*)d_in[3];
    const float* Wf  = (const float*)d_in[4];
    const float* bf  = (const float*)d_in[5];
    const float* Ws  = (const float*)d_in[6];
    const float* bs  = (const float*)d_in[7];
    const float* m1W0 = (const float*)d_in[8],  *m1b0 = (const float*)d_in[9];
    const float* m1W1 = (const float*)d_in[10], *m1b1 = (const float*)d_in[11];
    const float* m1Wp = (const float*)d_in[12], *m1bp = (const float*)d_in[13];
    const float* m2W0 = (const float*)d_in[14], *m2b0 = (const float*)d_in[15];
    const float* m2W1 = (const float*)d_in[16], *m2b1 = (const float*)d_in[17];
    const float* m2Wp = (const float*)d_in[18], *m2bp = (const float*)d_in[19];
    const float* oW   = (const float*)d_in[20], *ob   = (const float*)d_in[21];
    float* out = (float*)d_out;

    float *pH0, *pH1, *pT0, *pT1, *pW, *pB, *pPool, *pT0g, *pT1g, *pGf;
    __half* pPh;
    cudaGetSymbolAddress((void**)&pH0,  g_h0);
    cudaGetSymbolAddress((void**)&pH1,  g_h1);
    cudaGetSymbolAddress((void**)&pPh,  g_Ph);
    cudaGetSymbolAddress((void**)&pT0,  g_t0);
    cudaGetSymbolAddress((void**)&pT1,  g_t1);
    cudaGetSymbolAddress((void**)&pW,   g_Wcat);
    cudaGetSymbolAddress((void**)&pB,   g_bcat);
    cudaGetSymbolAddress((void**)&pPool, g_pool);
    cudaGetSymbolAddress((void**)&pT0g, g_t0g);
    cudaGetSymbolAddress((void**)&pT1g, g_t1g);
    cudaGetSymbolAddress((void**)&pGf,  g_gfin);

    cudaFuncSetAttribute(hmma_gemm, cudaFuncAttributeMaxDynamicSharedMemorySize, HMMA_SMEM);
    cudaFuncSetAttribute(hmma_gemm_half, cudaFuncAttributeMaxDynamicSharedMemorySize, HMMA_SMEM);

    const int MB = (NN + 127) / 128;   // 391
    const int EGRID = 304;             // 2 per SM on 152 SMs

    // --- CGConv layer 0 ---
    pack_wcat<<<(512 * 128 + 255) / 256, 256>>>(Wf, Ws, bf, bs, pW, pB, 0);
    hmma_gemm_half<<<dim3(4, MB), 256, HMMA_SMEM>>>(x, pW, pB, pPh, NN, 512, 128);
    copy_kernel<<<(NN * 32 + 255) / 256, 256>>>(x, pH0, NN * 32);
    edge_hmma_kernel<<<EGRID, 256>>>(pPh, ei, ea, Wf, Ws, 0, pH0);

    // --- CGConv layer 1 ---
    pack_wcat<<<(512 * 128 + 255) / 256, 256>>>(Wf, Ws, bf, bs, pW, pB, 1);
    hmma_gemm_half<<<dim3(4, MB), 256, HMMA_SMEM>>>(pH0, pW, pB, pPh, NN, 512, 128);
    copy_kernel<<<(NN * 32 + 255) / 256, 256>>>(pH0, pH1, NN * 32);
    edge_hmma_kernel<<<EGRID, 256>>>(pPh, ei, ea, Wf, Ws, 1, pH1);

    // --- node MLP (residual) ---
    hmma_gemm<<<dim3(2, MB), 256, HMMA_SMEM>>>(pH1, m1W0, m1b0, nullptr, pT0, NN, 256, 128, 1);
    hmma_gemm<<<dim3(2, MB), 256, HMMA_SMEM>>>(pT0, m1W1, m1b1, nullptr, pT1, NN, 256, 256, 1);
    hmma_gemm<<<dim3(1, MB), 256, HMMA_SMEM>>>(pT1, m1Wp, m1bp, pH1, pH0, NN, 128, 256, 0);

    // --- global add pool ---
    zero_kernel<<<(NG * 128 + 255) / 256, 256>>>(pPool, NG * 128);
    pool_kernel<<<(NN * 32 + 255) / 256, 256>>>(pH0, bat, pPool);

    // --- graph MLP (residual) + head ---
    sgemm_bt<<<dim3(2, 4), 256>>>(pPool, m2W0, m2b0, nullptr, pT0g, NG, 256, 128, 1);
    sgemm_bt<<<dim3(2, 4), 256>>>(pT0g, m2W1, m2b1, nullptr, pT1g, NG, 256, 256, 1);
    sgemm_bt<<<dim3(1, 4), 256>>>(pT1g, m2Wp, m2bp, pPool, pGf, NG, 128, 256, 0);
    out_kernel<<<64, 256>>>(pGf, oW, ob, out);
}

// round 16
// speedup vs baseline: 1.6179x; 1.2296x over previous
#include <cuda_runtime.h>
#include <cuda_fp16.h>
#include <cstdint>

#define NN 50000
#define NE 800000
#define NG 512

// ---------------- device scratch (static, no runtime alloc) ----------------
__device__ float  g_h0[NN * 128];
__device__ float  g_h1[NN * 128];
__device__ __half g_Ph[NN * 512];     // node projections in fp16 (51MB, L2-resident)
__device__ float  g_t0[NN * 256];
__device__ float  g_t1[NN * 256];
__device__ float  g_Wcat[512 * 128];
__device__ float  g_bcat[512];
__device__ float  g_pool[NG * 128];
__device__ float  g_t0g[NG * 256];
__device__ float  g_t1g[NG * 256];
__device__ float  g_gfin[NG * 128];

// ---------------- helpers ----------------
typedef unsigned long long u64;
__device__ __forceinline__ u64 pk2(float lo, float hi) {
    u64 r; asm("mov.b64 %0,{%1,%2};" : "=l"(r) : "f"(lo), "f"(hi)); return r;
}
__device__ __forceinline__ float2 up2(u64 v) {
    float2 r; asm("mov.b64 {%0,%1},%2;" : "=f"(r.x), "=f"(r.y) : "l"(v)); return r;
}
__device__ __forceinline__ u64 ffma2(u64 a, u64 b, u64 c) {
    u64 d; asm("fma.rn.f32x2 %0,%1,%2,%3;" : "=l"(d) : "l"(a), "l"(b), "l"(c)); return d;
}
union F4U { float4 f4; u64 u[2]; float f[4]; };

__device__ __forceinline__ void red4(float* addr, float4 v) {
    asm volatile("red.global.add.v4.f32 [%0], {%1,%2,%3,%4};"
                 :: "l"(addr), "f"(v.x), "f"(v.y), "f"(v.z), "f"(v.w) : "memory");
}
__device__ __forceinline__ void cpasync16(unsigned saddr, const void* gaddr) {
    asm volatile("cp.async.cg.shared.global [%0], [%1], 16;" :: "r"(saddr), "l"(gaddr));
}
__device__ __forceinline__ void cpcommit() { asm volatile("cp.async.commit_group;"); }
__device__ __forceinline__ void cpwait0()  { asm volatile("cp.async.wait_group 0;"); }

__device__ __forceinline__ float sigm(float x) { return 1.f / (1.f + __expf(-x)); }
__device__ __forceinline__ float softp(float x) {
    return fmaxf(x, 0.f) + __logf(1.f + __expf(-fabsf(x)));
}
__device__ __forceinline__ unsigned f2tf(float x) {
    unsigned r; asm("cvt.rna.tf32.f32 %0, %1;" : "=r"(r) : "f"(x)); return r;
}
__device__ __forceinline__ void mma_tf32_16n8k8(float* c, unsigned a0, unsigned a1,
                                                unsigned a2, unsigned a3,
                                                unsigned b0, unsigned b1) {
    asm volatile(
        "mma.sync.aligned.m16n8k8.row.col.f32.tf32.tf32.f32 "
        "{%0,%1,%2,%3}, {%4,%5,%6,%7}, {%8,%9}, {%0,%1,%2,%3};"
        : "+f"(c[0]), "+f"(c[1]), "+f"(c[2]), "+f"(c[3])
        : "r"(a0), "r"(a1), "r"(a2), "r"(a3), "r"(b0), "r"(b1));
}
__device__ __forceinline__ void mma_f16_16n8k16(float* c, unsigned a0, unsigned a1,
                                                unsigned a2, unsigned a3,
                                                unsigned b0, unsigned b1) {
    asm volatile(
        "mma.sync.aligned.m16n8k16.row.col.f32.f16.f16.f32 "
        "{%0,%1,%2,%3}, {%4,%5,%6,%7}, {%8,%9}, {%0,%1,%2,%3};"
        : "+f"(c[0]), "+f"(c[1]), "+f"(c[2]), "+f"(c[3])
        : "r"(a0), "r"(a1), "r"(a2), "r"(a3), "r"(b0), "r"(b1));
}
__device__ __forceinline__ unsigned h2pack(float lo, float hi) {
    __half2 h = __floats2half2_rn(lo, hi);
    return *(unsigned*)&h;
}

// ---------------- pack concatenated projection weights ----------------
__global__ void pack_wcat(const float* __restrict__ Wf, const float* __restrict__ Ws,
                          const float* __restrict__ bf, const float* __restrict__ bs,
                          float* __restrict__ Wcat, float* __restrict__ bcat, int layer) {
    int idx = blockIdx.x * blockDim.x + threadIdx.x;
    if (idx < 512) {
        float b = 0.f;
        if (idx < 128) b = bf[layer * 128 + idx];
        else if (idx < 256) b = bs[layer * 128 + idx - 128];
        bcat[idx] = b;
    }
    if (idx >= 512 * 128) return;
    int n = idx >> 7, k = idx & 127;
    const float* W; int o, koff;
    if      (n < 128) { W = Wf; o = n;       koff = 0;   }
    else if (n < 256) { W = Ws; o = n - 128; koff = 0;   }
    else if (n < 384) { W = Wf; o = n - 256; koff = 128; }
    else              { W = Ws; o = n - 384; koff = 128; }
    Wcat[idx] = W[((size_t)(layer * 128 + o)) * 320 + koff + k];
}

// ---------------- HMMA tf32 GEMM, f32 output (R10 win, unchanged) ----------------
#define GLDS 36
#define HMMA_SMEM (2 * 2 * 128 * GLDS * 4)   // 73728 bytes

__global__ void __launch_bounds__(256) hmma_gemm(
    const float* __restrict__ A, const float* __restrict__ B,
    const float* __restrict__ bias, const float* __restrict__ res,
    float* __restrict__ C, int M, int N, int K, int relu) {
    extern __shared__ float sm[];
    float* sA = sm;
    float* sB = sm + 2 * 128 * GLDS;
    unsigned saA = (unsigned)__cvta_generic_to_shared(sA);
    unsigned saB = (unsigned)__cvta_generic_to_shared(sB);

    int tid = threadIdx.x, wid = tid >> 5, lane = tid & 31;
    int warp_m = wid >> 2, warp_n = wid & 3;
    int r0 = lane >> 2, q = lane & 3;
    int m0 = blockIdx.y * 128, n0 = blockIdx.x * 128;

    auto stage = [&](int k0, int bb) {
#pragma unroll
        for (int t = 0; t < 4; t++) {
            int idx = tid + t * 256;
            int row = idx >> 3, c4 = idx & 7;
            int ar = m0 + row;
            if (ar < M)
                cpasync16(saA + (unsigned)(((bb * 128 + row) * GLDS + c4 * 4) * 4),
                          A + (size_t)ar * K + k0 + c4 * 4);
            cpasync16(saB + (unsigned)(((bb * 128 + row) * GLDS + c4 * 4) * 4),
                      B + (size_t)(n0 + row) * K + k0 + c4 * 4);
        }
    };

    float acc[4][4][4];
#pragma unroll
    for (int mt = 0; mt < 4; mt++)
#pragma unroll
        for (int nt = 0; nt < 4; nt++)
#pragma unroll
            for (int j = 0; j < 4; j++) acc[mt][nt][j] = 0.f;

    int nst = K >> 5;
    stage(0, 0); cpcommit();
    for (int s = 0; s < nst; s++) {
        cpwait0();
        __syncthreads();
        if (s + 1 < nst) { stage((s + 1) << 5, (s + 1) & 1); cpcommit(); }
        int bb = s & 1;
        const float* bA = sA + bb * 128 * GLDS;
        const float* bBp = sB + bb * 128 * GLDS;
#pragma unroll
        for (int ks = 0; ks < 4; ks++) {
            int k = ks * 8;
            unsigned af[4][4], bf4[4][2];
#pragma unroll
            for (int mt = 0; mt < 4; mt++) {
                const float* ap = bA + (warp_m * 64 + mt * 16 + r0) * GLDS + k + q;
                af[mt][0] = f2tf(ap[0]);
                af[mt][1] = f2tf(ap[8 * GLDS]);
                af[mt][2] = f2tf(ap[4]);
                af[mt][3] = f2tf(ap[8 * GLDS + 4]);
            }
#pragma unroll
            for (int nt = 0; nt < 4; nt++) {
                const float* bp = bBp + (warp_n * 32 + nt * 8 + r0) * GLDS + k + q;
                bf4[nt][0] = f2tf(bp[0]);
                bf4[nt][1] = f2tf(bp[4]);
            }
#pragma unroll
            for (int mt = 0; mt < 4; mt++)
#pragma unroll
                for (int nt = 0; nt < 4; nt++)
                    mma_tf32_16n8k8(acc[mt][nt], af[mt][0], af[mt][1], af[mt][2], af[mt][3],
                                    bf4[nt][0], bf4[nt][1]);
        }
        __syncthreads();
    }

#pragma unroll
    for (int mt = 0; mt < 4; mt++) {
#pragma unroll
        for (int half = 0; half < 2; half++) {
            int row = m0 + warp_m * 64 + mt * 16 + r0 + half * 8;
            if (row >= M) continue;
#pragma unroll
            for (int nt = 0; nt < 4; nt++) {
                int col = n0 + warp_n * 32 + nt * 8 + 2 * q;
                float v0 = acc[mt][nt][half * 2 + 0] + bias[col];
                float v1 = acc[mt][nt][half * 2 + 1] + bias[col + 1];
                if (res) {
                    float2 rv = *(const float2*)(res + (size_t)row * N + col);
                    v0 += rv.x; v1 += rv.y;
                }
                if (relu) { v0 = fmaxf(v0, 0.f); v1 = fmaxf(v1, 0.f); }
                *(float2*)(C + (size_t)row * N + col) = make_float2(v0, v1);
            }
        }
    }
}

// ---------------- HMMA tf32 GEMM, fp16 output (P producer) ----------------
__global__ void __launch_bounds__(256) hmma_gemm_half(
    const float* __restrict__ A, const float* __restrict__ B,
    const float* __restrict__ bias, __half* __restrict__ C,
    int M, int N, int K) {
    extern __shared__ float sm[];
    float* sA = sm;
    float* sB = sm + 2 * 128 * GLDS;
    unsigned saA = (unsigned)__cvta_generic_to_shared(sA);
    unsigned saB = (unsigned)__cvta_generic_to_shared(sB);

    int tid = threadIdx.x, wid = tid >> 5, lane = tid & 31;
    int warp_m = wid >> 2, warp_n = wid & 3;
    int r0 = lane >> 2, q = lane & 3;
    int m0 = blockIdx.y * 128, n0 = blockIdx.x * 128;

    auto stage = [&](int k0, int bb) {
#pragma unroll
        for (int t = 0; t < 4; t++) {
            int idx = tid + t * 256;
            int row = idx >> 3, c4 = idx & 7;
            int ar = m0 + row;
            if (ar < M)
                cpasync16(saA + (unsigned)(((bb * 128 + row) * GLDS + c4 * 4) * 4),
                          A + (size_t)ar * K + k0 + c4 * 4);
            cpasync16(saB + (unsigned)(((bb * 128 + row) * GLDS + c4 * 4) * 4),
                      B + (size_t)(n0 + row) * K + k0 + c4 * 4);
        }
    };

    float acc[4][4][4];
#pragma unroll
    for (int mt = 0; mt < 4; mt++)
#pragma unroll
        for (int nt = 0; nt < 4; nt++)
#pragma unroll
            for (int j = 0; j < 4; j++) acc[mt][nt][j] = 0.f;

    int nst = K >> 5;
    stage(0, 0); cpcommit();
    for (int s = 0; s < nst; s++) {
        cpwait0();
        __syncthreads();
        if (s + 1 < nst) { stage((s + 1) << 5, (s + 1) & 1); cpcommit(); }
        int bb = s & 1;
        const float* bA = sA + bb * 128 * GLDS;
        const float* bBp = sB + bb * 128 * GLDS;
#pragma unroll
        for (int ks = 0; ks < 4; ks++) {
            int k = ks * 8;
            unsigned af[4][4], bf4[4][2];
#pragma unroll
            for (int mt = 0; mt < 4; mt++) {
                const float* ap = bA + (warp_m * 64 + mt * 16 + r0) * GLDS + k + q;
                af[mt][0] = f2tf(ap[0]);
                af[mt][1] = f2tf(ap[8 * GLDS]);
                af[mt][2] = f2tf(ap[4]);
                af[mt][3] = f2tf(ap[8 * GLDS + 4]);
            }
#pragma unroll
            for (int nt = 0; nt < 4; nt++) {
                const float* bp = bBp + (warp_n * 32 + nt * 8 + r0) * GLDS + k + q;
                bf4[nt][0] = f2tf(bp[0]);
                bf4[nt][1] = f2tf(bp[4]);
            }
#pragma unroll
            for (int mt = 0; mt < 4; mt++)
#pragma unroll
                for (int nt = 0; nt < 4; nt++)
                    mma_tf32_16n8k8(acc[mt][nt], af[mt][0], af[mt][1], af[mt][2], af[mt][3],
                                    bf4[nt][0], bf4[nt][1]);
        }
        __syncthreads();
    }

#pragma unroll
    for (int mt = 0; mt < 4; mt++) {
#pragma unroll
        for (int half = 0; half < 2; half++) {
            int row = m0 + warp_m * 64 + mt * 16 + r0 + half * 8;
            if (row >= M) continue;
#pragma unroll
            for (int nt = 0; nt < 4; nt++) {
                int col = n0 + warp_n * 32 + nt * 8 + 2 * q;
                float v0 = acc[mt][nt][half * 2 + 0] + bias[col];
                float v1 = acc[mt][nt][half * 2 + 1] + bias[col + 1];
                *(__half2*)(C + (size_t)row * N + col) = __floats2half2_rn(v0, v1);
            }
        }
    }
}

// ---------------- SGEMM fp32 (graph-level, small) ----------------
__global__ void __launch_bounds__(256) sgemm_bt(
    const float* __restrict__ A, const float* __restrict__ B,
    const float* __restrict__ bias, const float* __restrict__ res,
    float* __restrict__ C, int M, int N, int K, int relu) {
    __shared__ float As[8][128];
    __shared__ float Bs[8][128];
    int tid = threadIdx.x;
    int m0 = blockIdx.y * 128;
    int n0 = blockIdx.x * 128;
    int tx = tid & 15, ty = tid >> 4;
    int lr = tid >> 1;
    int lk = (tid & 1) * 4;

    u64 acc[8][4];
#pragma unroll
    for (int i = 0; i < 8; i++)
#pragma unroll
        for (int j = 0; j < 4; j++) acc[i][j] = 0ull;

    for (int k0 = 0; k0 < K; k0 += 8) {
        float4 av = make_float4(0.f, 0.f, 0.f, 0.f);
        int arow = m0 + lr;
        if (arow < M) av = *(const float4*)(A + (size_t)arow * K + k0 + lk);
        As[lk + 0][lr] = av.x; As[lk + 1][lr] = av.y;
        As[lk + 2][lr] = av.z; As[lk + 3][lr] = av.w;
        float4 bv = *(const float4*)(B + (size_t)(n0 + lr) * K + k0 + lk);
        Bs[lk + 0][lr] = bv.x; Bs[lk + 1][lr] = bv.y;
        Bs[lk + 2][lr] = bv.z; Bs[lk + 3][lr] = bv.w;
        __syncthreads();
#pragma unroll
        for (int k = 0; k < 8; k++) {
            F4U b0, b1;
            b0.f4 = *(const float4*)&Bs[k][tx * 8];
            b1.f4 = *(const float4*)&Bs[k][tx * 8 + 4];
            float4 a0 = *(const float4*)&As[k][ty * 8];
            float4 a1 = *(const float4*)&As[k][ty * 8 + 4];
            float a[8] = {a0.x, a0.y, a0.z, a0.w, a1.x, a1.y, a1.z, a1.w};
#pragma unroll
            for (int i = 0; i < 8; i++) {
                u64 ai = pk2(a[i], a[i]);
                acc[i][0] = ffma2(ai, b0.u[0], acc[i][0]);
                acc[i][1] = ffma2(ai, b0.u[1], acc[i][1]);
                acc[i][2] = ffma2(ai, b1.u[0], acc[i][2]);
                acc[i][3] = ffma2(ai, b1.u[1], acc[i][3]);
            }
        }
        __syncthreads();
    }

#pragma unroll
    for (int i = 0; i < 8; i++) {
        int row = m0 + ty * 8 + i;
        if (row >= M) continue;
        int n = n0 + tx * 8;
        float o[8];
#pragma unroll
        for (int j2 = 0; j2 < 4; j2++) {
            float2 v = up2(acc[i][j2]);
            o[2 * j2] = v.x; o[2 * j2 + 1] = v.y;
        }
#pragma unroll
        for (int j = 0; j < 8; j++) {
            float v = o[j] + bias[n + j];
            if (res) v += res[(size_t)row * N + n + j];
            if (relu) v = fmaxf(v, 0.f);
            o[j] = v;
        }
        *(float4*)(C + (size_t)row * N + n)     = make_float4(o[0], o[1], o[2], o[3]);
        *(float4*)(C + (size_t)row * N + n + 4) = make_float4(o[4], o[5], o[6], o[7]);
    }
}

// ---------------- edge kernel v12: fp16 HMMA (m16n8k16) + two-phase epilogue, 3 CTAs/SM ----------------
__global__ void __launch_bounds__(256, 3) edge_hmma_kernel(
    const __half* __restrict__ Pall, const int* __restrict__ ei,
    const float* __restrict__ ea, const float* __restrict__ Wf,
    const float* __restrict__ Ws, int layer, float* __restrict__ hout) {
    __shared__ float sAcc[16 * 264];
    __shared__ float sEa[2][16][68];
    __shared__ int sIdx[2][32];

    int tid = threadIdx.x, w = tid >> 5, lane = tid & 31;
    int q = lane & 3, r0 = lane >> 2;

    // persistent B fragments, fp16-packed: 4 nt x 4 ks(x16) x 2 regs = 32 regs
    unsigned bfr[4][4][2];
#pragma unroll
    for (int nt = 0; nt < 4; nt++) {
        int j = w * 16 + (nt & 1) * 8 + r0;
        const float* Wp = ((nt < 2) ? Wf : Ws) + (size_t)(layer * 128 + j) * 320 + 256;
#pragma unroll
        for (int ks = 0; ks < 4; ks++) {
            int k0 = ks * 16;
            bfr[nt][ks][0] = h2pack(__ldg(Wp + k0 + 2 * q),     __ldg(Wp + k0 + 2 * q + 1));
            bfr[nt][ks][1] = h2pack(__ldg(Wp + k0 + 2 * q + 8), __ldg(Wp + k0 + 2 * q + 9));
        }
    }

    const int NT = NE / 16;
    int nbs = gridDim.x;
    int tile = blockIdx.x;

    auto stage = [&](int t, int bb) {
        int e0 = t << 4;
        int row = tid >> 4, ch = tid & 15;
        unsigned daddr = (unsigned)__cvta_generic_to_shared(&sEa[bb][row][0]) + ch * 16;
        cpasync16(daddr, ea + (size_t)(e0 + row) * 64 + ch * 4);
        if (tid < 32) sIdx[bb][tid] = __ldg(ei + (tid < 16 ? 0 : NE) + e0 + (tid & 15));
    };

    if (tile < NT) stage(tile, 0);
    cpcommit();

    int buf = 0;
    for (; tile < NT; tile += nbs) {
        cpwait0();
        __syncthreads();                 // EA(tile) visible; prev phase-2 done
        int nxt = tile + nbs;
        if (nxt < NT) stage(nxt, buf ^ 1);
        cpcommit();

        // ---- phase 1: fp16 tensor-core GEMM (4 k-steps of 16) ----
        float acc[4][4];
#pragma unroll
        for (int nt = 0; nt < 4; nt++)
#pragma unroll
            for (int j = 0; j < 4; j++) acc[nt][j] = 0.f;

#pragma unroll
        for (int ks = 0; ks < 4; ks++) {
            int k0 = ks * 16;
            float2 va0 = *(const float2*)&sEa[buf][r0][k0 + 2 * q];
            float2 va1 = *(const float2*)&sEa[buf][r0 + 8][k0 + 2 * q];
            float2 va2 = *(const float2*)&sEa[buf][r0][k0 + 2 * q + 8];
            float2 va3 = *(const float2*)&sEa[buf][r0 + 8][k0 + 2 * q + 8];
            unsigned a0 = h2pack(va0.x, va0.y);
            unsigned a1 = h2pack(va1.x, va1.y);
            unsigned a2 = h2pack(va2.x, va2.y);
            unsigned a3 = h2pack(va3.x, va3.y);
#pragma unroll
            for (int nt = 0; nt < 4; nt++)
                mma_f16_16n8k16(acc[nt], a0, a1, a2, a3, bfr[nt][ks][0], bfr[nt][ks][1]);
        }

        // STS accumulators into edge-major tile
#pragma unroll
        for (int nt = 0; nt < 4; nt++) {
            int base = (nt < 2) ? 0 : 128;
            int c = w * 16 + (nt & 1) * 8 + 2 * q;
#pragma unroll
            for (int half = 0; half < 2; half++) {
                int row = r0 + half * 8;
                *(float2*)&sAcc[row * 264 + base + c] =
                    make_float2(acc[nt][half * 2], acc[nt][half * 2 + 1]);
            }
        }
        __syncthreads();

        // ---- phase 2: one edge per warp-pass, coalesced fp16 gathers ----
#pragma unroll
        for (int t = 0; t < 2; t++) {
            int e = w * 2 + t;
            int sN = sIdx[buf][e], dN = sIdx[buf][16 + e];
            int c = lane * 4;
            float4 f4 = *(float4*)&sAcc[e * 264 + c];
            float4 s4 = *(float4*)&sAcc[e * 264 + 128 + c];
            const __half* pd = Pall + (size_t)dN * 512;
            const __half* ps = Pall + (size_t)sN * 512;
            uint2 vfd = *(const uint2*)(pd + c);
            uint2 vsd = *(const uint2*)(pd + 128 + c);
            uint2 vfs = *(const uint2*)(ps + 256 + c);
            uint2 vss = *(const uint2*)(ps + 384 + c);
            float2 fd0 = __half22float2(*(__half2*)&vfd.x), fd1 = __half22float2(*(__half2*)&vfd.y);
            float2 sd0 = __half22float2(*(__half2*)&vsd.x), sd1 = __half22float2(*(__half2*)&vsd.y);
            float2 fs0 = __half22float2(*(__half2*)&vfs.x), fs1 = __half22float2(*(__half2*)&vfs.y);
            float2 ss0 = __half22float2(*(__half2*)&vss.x), ss1 = __half22float2(*(__half2*)&vss.y);
            float4 m;
            m.x = sigm(f4.x + fd0.x + fs0.x) * softp(s4.x + sd0.x + ss0.x);
            m.y = sigm(f4.y + fd0.y + fs0.y) * softp(s4.y + sd0.y + ss0.y);
            m.z = sigm(f4.z + fd1.x + fs1.x) * softp(s4.z + sd1.x + ss1.x);
            m.w = sigm(f4.w + fd1.y + fs1.y) * softp(s4.w + sd1.y + ss1.y);
            red4(hout + (size_t)dN * 128 + c, m);
        }
        buf ^= 1;
    }
}

// ---------------- small utility kernels ----------------
__global__ void copy_kernel(const float* __restrict__ a, float* __restrict__ b, int n4) {
    int i = blockIdx.x * blockDim.x + threadIdx.x;
    if (i < n4) ((float4*)b)[i] = ((const float4*)a)[i];
}
__global__ void zero_kernel(float* __restrict__ p, int n) {
    int i = blockIdx.x * blockDim.x + threadIdx.x;
    if (i < n) p[i] = 0.f;
}
__global__ void pool_kernel(const float* __restrict__ h, const int* __restrict__ batch,
                            float* __restrict__ g) {
    int idx = blockIdx.x * blockDim.x + threadIdx.x;
    if (idx >= NN * 32) return;
    int node = idx >> 5, qq = idx & 31;
    float4 v = ((const float4*)h)[idx];
    red4(g + (size_t)batch[node] * 128 + qq * 4, v);
}
__global__ void out_kernel(const float* __restrict__ gf, const float* __restrict__ oW,
                           const float* __restrict__ ob, float* __restrict__ out) {
    int gidx = blockIdx.x * 8 + (threadIdx.x >> 5);
    int lane = threadIdx.x & 31;
    if (gidx >= NG) return;
    float s = 0.f;
#pragma unroll
    for (int k = lane; k < 128; k += 32) s += gf[gidx * 128 + k] * oW[k];
#pragma unroll
    for (int o = 16; o; o >>= 1) s += __shfl_down_sync(0xffffffffu, s, o);
    if (lane == 0) out[gidx] = s + ob[0];
}

// ---------------- launch ----------------
extern "C" void kernel_launch(void* const* d_in, const int* in_sizes, int n_in,
                              void* d_out, int out_size) {
    (void)in_sizes; (void)n_in; (void)out_size;
    const float* x   = (const float*)d_in[0];
    const int*   ei  = (const int*)d_in[1];
    const float* ea  = (const float*)d_in[2];
    const int*   bat = (const int*)d_in[3];
    const float* Wf  = (const float*)d_in[4];
    const float* bf  = (const float*)d_in[5];
    const float* Ws  = (const float*)d_in[6];
    const float* bs  = (const float*)d_in[7];
    const float* m1W0 = (const float*)d_in[8],  *m1b0 = (const float*)d_in[9];
    const float* m1W1 = (const float*)d_in[10], *m1b1 = (const float*)d_in[11];
    const float* m1Wp = (const float*)d_in[12], *m1bp = (const float*)d_in[13];
    const float* m2W0 = (const float*)d_in[14], *m2b0 = (const float*)d_in[15];
    const float* m2W1 = (const float*)d_in[16], *m2b1 = (const float*)d_in[17];
    const float* m2Wp = (const float*)d_in[18], *m2bp = (const float*)d_in[19];
    const float* oW   = (const float*)d_in[20], *ob   = (const float*)d_in[21];
    float* out = (float*)d_out;

    float *pH0, *pH1, *pT0, *pT1, *pW, *pB, *pPool, *pT0g, *pT1g, *pGf;
    __half* pPh;
    cudaGetSymbolAddress((void**)&pH0,  g_h0);
    cudaGetSymbolAddress((void**)&pH1,  g_h1);
    cudaGetSymbolAddress((void**)&pPh,  g_Ph);
    cudaGetSymbolAddress((void**)&pT0,  g_t0);
    cudaGetSymbolAddress((void**)&pT1,  g_t1);
    cudaGetSymbolAddress((void**)&pW,   g_Wcat);
    cudaGetSymbolAddress((void**)&pB,   g_bcat);
    cudaGetSymbolAddress((void**)&pPool, g_pool);
    cudaGetSymbolAddress((void**)&pT0g, g_t0g);
    cudaGetSymbolAddress((void**)&pT1g, g_t1g);
    cudaGetSymbolAddress((void**)&pGf,  g_gfin);

    cudaFuncSetAttribute(hmma_gemm, cudaFuncAttributeMaxDynamicSharedMemorySize, HMMA_SMEM);
    cudaFuncSetAttribute(hmma_gemm_half, cudaFuncAttributeMaxDynamicSharedMemorySize, HMMA_SMEM);

    const int MB = (NN + 127) / 128;   // 391
    const int EGRID = 456;             // 3 per SM on 152 SMs

    // --- CGConv layer 0 ---
    pack_wcat<<<(512 * 128 + 255) / 256, 256>>>(Wf, Ws, bf, bs, pW, pB, 0);
    hmma_gemm_half<<<dim3(4, MB), 256, HMMA_SMEM>>>(x, pW, pB, pPh, NN, 512, 128);
    copy_kernel<<<(NN * 32 + 255) / 256, 256>>>(x, pH0, NN * 32);
    edge_hmma_kernel<<<EGRID, 256>>>(pPh, ei, ea, Wf, Ws, 0, pH0);

    // --- CGConv layer 1 ---
    pack_wcat<<<(512 * 128 + 255) / 256, 256>>>(Wf, Ws, bf, bs, pW, pB, 1);
    hmma_gemm_half<<<dim3(4, MB), 256, HMMA_SMEM>>>(pH0, pW, pB, pPh, NN, 512, 128);
    copy_kernel<<<(NN * 32 + 255) / 256, 256>>>(pH0, pH1, NN * 32);
    edge_hmma_kernel<<<EGRID, 256>>>(pPh, ei, ea, Wf, Ws, 1, pH1);

    // --- node MLP (residual) ---
    hmma_gemm<<<dim3(2, MB), 256, HMMA_SMEM>>>(pH1, m1W0, m1b0, nullptr, pT0, NN, 256, 128, 1);
    hmma_gemm<<<dim3(2, MB), 256, HMMA_SMEM>>>(pT0, m1W1, m1b1, nullptr, pT1, NN, 256, 256, 1);
    hmma_gemm<<<dim3(1, MB), 256, HMMA_SMEM>>>(pT1, m1Wp, m1bp, pH1, pH0, NN, 128, 256, 0);

    // --- global add pool ---
    zero_kernel<<<(NG * 128 + 255) / 256, 256>>>(pPool, NG * 128);
    pool_kernel<<<(NN * 32 + 255) / 256, 256>>>(pH0, bat, pPool);

    // --- graph MLP (residual) + head ---
    sgemm_bt<<<dim3(2, 4), 256>>>(pPool, m2W0, m2b0, nullptr, pT0g, NG, 256, 128, 1);
    sgemm_bt<<<dim3(2, 4), 256>>>(pT0g, m2W1, m2b1, nullptr, pT1g, NG, 256, 256, 1);
    sgemm_bt<<<dim3(1, 4), 256>>>(pT1g, m2Wp, m2bp, pPool, pGf, NG, 128, 256, 0);
    out_kernel<<<64, 256>>>(pGf, oW, ob, out);
}